// round 9
// baseline (speedup 1.0000x reference)
#include <cuda_runtime.h>
#include <cuda_bf16.h>
#include <math.h>
#include <stdint.h>

// Problem dims (fixed by the dataset)
#define DD    192
#define HDIM  12
#define SEQ   8192
#define BATCH 16
#define NROWS (BATCH * SEQ)
#define WELTS (DD * DD)         // 36864 elements per weight
#define APLANE ((size_t)NROWS * DD)

// ---------------- scratch (static device globals) -------------------------
__device__ float g_q[(size_t)NROWS * DD];
__device__ float g_k[(size_t)NROWS * DD];
__device__ float g_v[(size_t)NROWS * DD];
// bf16 hi/lo planes (plane 0 = hi at offset 0, plane 1 = lo at +APLANE)
__device__ __nv_bfloat16 g_xsplit[(size_t)2 * NROWS * DD];
__device__ __nv_bfloat16 g_ctxsplit[(size_t)2 * NROWS * DD];
// bf16 hi/lo planes for Wq,Wk,Wv,Wo: plane index = w*2 + (0=hi,1=lo)
__device__ __nv_bfloat16 g_wsplit[(size_t)8 * WELTS];

// ---------------- helpers --------------------------------------------------
__device__ __forceinline__ uint32_t pack_bf2(__nv_bfloat16 a, __nv_bfloat16 b) {
    return (uint32_t)__bfloat16_as_ushort(a) |
           ((uint32_t)__bfloat16_as_ushort(b) << 16);
}
__device__ __forceinline__ void split2(float x, __nv_bfloat16& hi, __nv_bfloat16& lo) {
    hi = __float2bfloat16(x);
    lo = __float2bfloat16(x - __bfloat162float(hi));
}

// bf16 m16n8k16 mma, fp32 accumulate
__device__ __forceinline__ void mma16(float* c, const uint32_t* a, const uint32_t* b) {
    asm volatile(
        "mma.sync.aligned.m16n8k16.row.col.f32.bf16.bf16.f32 "
        "{%0,%1,%2,%3}, {%4,%5,%6,%7}, {%8,%9}, {%0,%1,%2,%3};"
        : "+f"(c[0]), "+f"(c[1]), "+f"(c[2]), "+f"(c[3])
        : "r"(a[0]), "r"(a[1]), "r"(a[2]), "r"(a[3]), "r"(b[0]), "r"(b[1]));
}

// ---------------- prep: split weights / activations ------------------------
__global__ __launch_bounds__(256)
void split_weights(const float* __restrict__ Wq, const float* __restrict__ Wk,
                   const float* __restrict__ Wv, const float* __restrict__ Wo)
{
    int f = blockIdx.x * 256 + threadIdx.x;     // float4 index
    int w  = f / (WELTS / 4);
    int e4 = (f - w * (WELTS / 4)) * 4;
    const float* W = (w == 0) ? Wq : (w == 1) ? Wk : (w == 2) ? Wv : Wo;
    float4 a = *(const float4*)&W[e4];
    __nv_bfloat16 h0,h1,h2,h3,l0,l1,l2,l3;
    split2(a.x,h0,l0); split2(a.y,h1,l1); split2(a.z,h2,l2); split2(a.w,h3,l3);
    uint2 hp, lp;
    hp.x = pack_bf2(h0,h1); hp.y = pack_bf2(h2,h3);
    lp.x = pack_bf2(l0,l1); lp.y = pack_bf2(l2,l3);
    *(uint2*)&g_wsplit[(size_t)(w*2)   * WELTS + e4] = hp;
    *(uint2*)&g_wsplit[(size_t)(w*2+1) * WELTS + e4] = lp;
}

__global__ __launch_bounds__(256)
void split_x(const float* __restrict__ x)
{
    size_t f = (size_t)blockIdx.x * 256 + threadIdx.x;   // float4 index
    float4 a = ((const float4*)x)[f];
    __nv_bfloat16 h0,h1,h2,h3,l0,l1,l2,l3;
    split2(a.x,h0,l0); split2(a.y,h1,l1); split2(a.z,h2,l2); split2(a.w,h3,l3);
    uint2 hp, lp;
    hp.x = pack_bf2(h0,h1); hp.y = pack_bf2(h2,h3);
    lp.x = pack_bf2(l0,l1); lp.y = pack_bf2(l2,l3);
    ((uint2*)g_xsplit)[f] = hp;
    ((uint2*)(g_xsplit + APLANE))[f] = lp;
}

// ---------------- GEMM: bf16 3-split, double-buffered pipeline -------------
// out[seg][r, c] = (sum_k A[r,k] * W[seg][c,k] + bias[seg][c]) * scale[seg]
//                  (+ res[r,c] if res)  where seg = blockIdx.x / 3.
#define BM 128
#define BN 64
#define BK 32
#define PADW 20                    // uint32 (bf16-pair) row stride
#define SM_AH 0
#define SM_AL (BM * PADW)          // 2560
#define SM_BH (2 * BM * PADW)      // 5120
#define SM_BL (2 * BM * PADW + BN * PADW)
#define BUFW  (2 * BM * PADW + 2 * BN * PADW)   // 7680 uint32 per buffer
#define GEMM_SMEM (2 * BUFW * 4)                // 61440 bytes

struct GemmArgs {
    int          plane[3];  // hi plane index in g_wsplit (lo = +1)
    const float* bias[3];
    float*       out[3];
    float        scale[3];
    const float* res;
};

__global__ __launch_bounds__(256, 2)
void gemm_bf16(const __nv_bfloat16* __restrict__ Abase, GemmArgs args)
{
    extern __shared__ uint32_t smem[];          // 2 * BUFW

    const int col0g = blockIdx.x * BN;
    const int seg   = col0g / DD;
    const int lc0   = col0g - seg * DD;
    const int row0  = blockIdx.y * BM;

    const uint4* __restrict__ A4 = (const uint4*)Abase;            // 24 uint4/row
    const uint4* __restrict__ W4 =
        (const uint4*)(g_wsplit + (size_t)args.plane[seg] * WELTS);

    const int tid  = threadIdx.x;
    const int lane = tid & 31;
    const int warp = tid >> 5;
    const int wm   = (warp & 3) * 32;   // 4 warps in m
    const int wn   = (warp >> 2) * 32;  // 2 warps in n
    const int g    = lane >> 2;
    const int t    = lane & 3;

    float acc[2][4][4];
    #pragma unroll
    for (int i = 0; i < 2; i++)
        #pragma unroll
        for (int j = 0; j < 4; j++)
            #pragma unroll
            for (int c = 0; c < 4; c++) acc[i][j][c] = 0.f;

    // ---- staging helpers (pure copies; planes pre-converted) --------------
    auto load_chunk = [&](int c, uint4* na, uint4* nb) {
        #pragma unroll
        for (int i = 0; i < 4; i++) {
            int idx = tid + i * 256;
            int pl = idx >> 9, rem = idx & 511;
            int m = rem >> 2, q4 = rem & 3;
            na[i] = A4[(size_t)pl * (APLANE / 8) + (size_t)(row0 + m) * 24 + c * 4 + q4];
        }
        #pragma unroll
        for (int i = 0; i < 2; i++) {
            int idx = tid + i * 256;
            int pl = idx >> 8, rem = idx & 255;
            int n = rem >> 2, q4 = rem & 3;
            nb[i] = W4[(size_t)pl * (WELTS / 8) + (size_t)(lc0 + n) * 24 + c * 4 + q4];
        }
    };
    auto store_chunk = [&](uint32_t* buf, const uint4* na, const uint4* nb) {
        #pragma unroll
        for (int i = 0; i < 4; i++) {
            int idx = tid + i * 256;
            int pl = idx >> 9, rem = idx & 511;
            int m = rem >> 2, q4 = rem & 3;
            *(uint4*)&buf[(pl ? SM_AL : SM_AH) + m * PADW + q4 * 4] = na[i];
        }
        #pragma unroll
        for (int i = 0; i < 2; i++) {
            int idx = tid + i * 256;
            int pl = idx >> 8, rem = idx & 255;
            int n = rem >> 2, q4 = rem & 3;
            *(uint4*)&buf[(pl ? SM_BL : SM_BH) + n * PADW + q4 * 4] = nb[i];
        }
    };

    // ---- prologue ----------------------------------------------------------
    {
        uint4 pa[4], pb[2];
        load_chunk(0, pa, pb);
        store_chunk(smem, pa, pb);
    }
    __syncthreads();

    // ---- pipelined main loop over 6 chunks ---------------------------------
    #pragma unroll
    for (int c = 0; c < 6; c++) {
        uint32_t* cur = smem + (c & 1) * BUFW;
        uint32_t* nxt = smem + ((c + 1) & 1) * BUFW;
        uint4 na[4], nb[2];
        if (c < 5) load_chunk(c + 1, na, nb);

        #pragma unroll
        for (int ks = 0; ks < 2; ks++) {
            const int kpb = ks * 8;
            uint32_t ah[2][4], al[2][4];
            #pragma unroll
            for (int mt = 0; mt < 2; mt++) {
                int o = (wm + mt * 16 + g) * PADW + kpb + t;
                ah[mt][0] = cur[SM_AH + o];
                ah[mt][1] = cur[SM_AH + o + 8 * PADW];
                ah[mt][2] = cur[SM_AH + o + 4];
                ah[mt][3] = cur[SM_AH + o + 8 * PADW + 4];
                al[mt][0] = cur[SM_AL + o];
                al[mt][1] = cur[SM_AL + o + 8 * PADW];
                al[mt][2] = cur[SM_AL + o + 4];
                al[mt][3] = cur[SM_AL + o + 8 * PADW + 4];
            }
            uint32_t bh[4][2], bl[4][2];
            #pragma unroll
            for (int nt = 0; nt < 4; nt++) {
                int o = (wn + nt * 8 + g) * PADW + kpb + t;
                bh[nt][0] = cur[SM_BH + o];
                bh[nt][1] = cur[SM_BH + o + 4];
                bl[nt][0] = cur[SM_BL + o];
                bl[nt][1] = cur[SM_BL + o + 4];
            }
            // Pass-outer ordering: each accumulator touched once per pass ->
            // 8 independent MMAs between RAW reuses of any accumulator.
            // Per-acc accumulation order unchanged (al*bh, ah*bl, ah*bh).
            #pragma unroll
            for (int mt = 0; mt < 2; mt++)
                #pragma unroll
                for (int nt = 0; nt < 4; nt++)
                    mma16(acc[mt][nt], al[mt], bh[nt]);
            #pragma unroll
            for (int mt = 0; mt < 2; mt++)
                #pragma unroll
                for (int nt = 0; nt < 4; nt++)
                    mma16(acc[mt][nt], ah[mt], bl[nt]);
            #pragma unroll
            for (int mt = 0; mt < 2; mt++)
                #pragma unroll
                for (int nt = 0; nt < 4; nt++)
                    mma16(acc[mt][nt], ah[mt], bh[nt]);
        }

        if (c < 5) store_chunk(nxt, na, nb);
        __syncthreads();
    }

    // ---- epilogue ----------------------------------------------------------
    const float scale = args.scale[seg];
    float* const outp = args.out[seg];
    const float* const bias = args.bias[seg];
    const float* const res  = args.res;

    #pragma unroll
    for (int mt = 0; mt < 2; mt++) {
        #pragma unroll
        for (int nt = 0; nt < 4; nt++) {
            int row = row0 + wm + mt * 16 + g;
            int col = lc0 + wn + nt * 8 + t * 2;
            float b0 = bias[col], b1 = bias[col + 1];
            #pragma unroll
            for (int half = 0; half < 2; half++) {
                int r = row + half * 8;
                float v0 = (acc[mt][nt][half * 2 + 0] + b0) * scale;
                float v1 = (acc[mt][nt][half * 2 + 1] + b1) * scale;
                if (res != nullptr) {
                    const float2 rv = *(const float2*)&res[(size_t)r * DD + col];
                    v0 += rv.x; v1 += rv.y;
                }
                float2 o; o.x = v0; o.y = v1;
                *(float2*)&outp[(size_t)r * DD + col] = o;
            }
        }
    }
}

// ---------------- banded attention: window d in [-2, 2] --------------------
#define TS 16
#define KVROWS (TS + 4)

__global__ __launch_bounds__(256)
void band_attn(const float* __restrict__ mask0)
{
    __shared__ float ks[KVROWS * DD];
    __shared__ float vs[KVROWS * DD];
    __shared__ float msk[KVROWS];

    const int chunk = blockIdx.x;
    const int b  = chunk / (SEQ / TS);
    const int s0 = (chunk % (SEQ / TS)) * TS;
    const int tid = threadIdx.x;

    for (int i4 = tid; i4 < KVROWS * (DD / 4); i4 += 256) {
        int r  = i4 / (DD / 4);
        int c4 = i4 % (DD / 4);
        int s  = s0 - 2 + r;
        float4 kv = make_float4(0.f, 0.f, 0.f, 0.f);
        float4 vv = make_float4(0.f, 0.f, 0.f, 0.f);
        if (s >= 0 && s < SEQ) {
            size_t off = (size_t)(b * SEQ + s) * DD + c4 * 4;
            kv = *(const float4*)&g_k[off];
            vv = *(const float4*)&g_v[off];
        }
        *(float4*)&ks[r * DD + c4 * 4] = kv;
        *(float4*)&vs[r * DD + c4 * 4] = vv;
    }
    if (tid < KVROWS) {
        int s = s0 - 2 + tid;
        msk[tid] = (s >= 0 && s < SEQ) ? mask0[b * SEQ + s] : 0.f;
    }
    __syncthreads();

    const int sl = tid >> 4;
    const int h  = tid & 15;
    const int s  = s0 + sl;

    float q[HDIM];
    {
        const float* qp = &g_q[(size_t)(b * SEQ + s) * DD + h * HDIM];
        float4 q0 = *(const float4*)(qp + 0);
        float4 q1 = *(const float4*)(qp + 4);
        float4 q2 = *(const float4*)(qp + 8);
        q[0]=q0.x; q[1]=q0.y; q[2]=q0.z;  q[3]=q0.w;
        q[4]=q1.x; q[5]=q1.y; q[6]=q1.z;  q[7]=q1.w;
        q[8]=q2.x; q[9]=q2.y; q[10]=q2.z; q[11]=q2.w;
    }

    const float NEG  = -3.402823466e38f;
    const float NINF = __int_as_float(0xff800000);

    float sc[5];
    #pragma unroll
    for (int d = 0; d < 5; d++) {
        int r = sl + d;
        int skey = s + d - 2;
        const float* kp = &ks[r * DD + h * HDIM];
        float dot = 0.f;
        #pragma unroll
        for (int j = 0; j < HDIM; j++) dot += q[j] * kp[j];
        float fm = (msk[r] != 0.f) ? NEG : 0.f;
        sc[d] = (skey >= 0 && skey < SEQ) ? (dot + fm) : NINF;
    }

    float mx = sc[0];
    #pragma unroll
    for (int d = 1; d < 5; d++) mx = fmaxf(mx, sc[d]);
    float e[5], sum = 0.f;
    #pragma unroll
    for (int d = 0; d < 5; d++) { e[d] = expf(sc[d] - mx); sum += e[d]; }
    float inv = 1.f / sum;
    bool index_masked = (msk[sl + 2] < 0.f);

    float c[HDIM] = {};
    #pragma unroll
    for (int d = 0; d < 5; d++) {
        float p = index_masked ? 0.f : e[d] * inv;
        const float* vp = &vs[(sl + d) * DD + h * HDIM];
        #pragma unroll
        for (int j = 0; j < HDIM; j++) c[j] += p * vp[j];
    }

    // write ctx directly as bf16 hi/lo planes for the O-projection
    // HDIM = 12 bf16 values = 6 packed uint32 per plane
    __nv_bfloat16 chi[HDIM], clo[HDIM];
    #pragma unroll
    for (int j = 0; j < HDIM; j++) split2(c[j], chi[j], clo[j]);
    size_t base = (size_t)(b * SEQ + s) * DD + h * HDIM;
    uint32_t* oh = (uint32_t*)(g_ctxsplit + base);
    uint32_t* ol = (uint32_t*)(g_ctxsplit + APLANE + base);
    #pragma unroll
    for (int j = 0; j < 6; j++) {
        oh[j] = pack_bf2(chi[2*j], chi[2*j+1]);
        ol[j] = pack_bf2(clo[2*j], clo[2*j+1]);
    }
}

// ---------------- LayerNorm over the last dim (192), warp per row ----------
__global__ __launch_bounds__(256)
void layernorm(const float* __restrict__ ln_g, const float* __restrict__ ln_b,
               float* __restrict__ out)
{
    const int row  = blockIdx.x * 8 + (threadIdx.x >> 5);
    const int lane = threadIdx.x & 31;

    const float* hp = &g_q[(size_t)row * DD];  // g_q holds h after O-proj
    float h[6];
    float sum = 0.f;
    #pragma unroll
    for (int j = 0; j < 6; j++) { h[j] = hp[lane + j * 32]; sum += h[j]; }
    #pragma unroll
    for (int o = 16; o > 0; o >>= 1) sum += __shfl_xor_sync(0xffffffffu, sum, o);
    float mu = sum * (1.f / 192.f);

    float s2 = 0.f;
    #pragma unroll
    for (int j = 0; j < 6; j++) { float d = h[j] - mu; s2 += d * d; }
    #pragma unroll
    for (int o = 16; o > 0; o >>= 1) s2 += __shfl_xor_sync(0xffffffffu, s2, o);
    float invstd = rsqrtf(s2 * (1.f / 192.f) + 1e-12f);

    float* op = &out[(size_t)row * DD];
    #pragma unroll
    for (int j = 0; j < 6; j++) {
        int cc = lane + j * 32;
        op[cc] = (h[j] - mu) * invstd * ln_g[cc] + ln_b[cc];
    }
}

// ---------------- launch ---------------------------------------------------
extern "C" void kernel_launch(void* const* d_in, const int* in_sizes, int n_in,
                              void* d_out, int out_size)
{
    const float* x     = (const float*)d_in[0];
    const float* mask0 = (const float*)d_in[1];
    const float* bq    = (const float*)d_in[3];
    const float* bk    = (const float*)d_in[5];
    const float* bv    = (const float*)d_in[7];
    const float* bo    = (const float*)d_in[9];
    const float* ln_g  = (const float*)d_in[10];
    const float* ln_b  = (const float*)d_in[11];
    float* out = (float*)d_out;

    float *pq, *pk, *pv;
    __nv_bfloat16 *pxs, *pcs;
    cudaGetSymbolAddress((void**)&pq,  g_q);
    cudaGetSymbolAddress((void**)&pk,  g_k);
    cudaGetSymbolAddress((void**)&pv,  g_v);
    cudaGetSymbolAddress((void**)&pxs, g_xsplit);
    cudaGetSymbolAddress((void**)&pcs, g_ctxsplit);

    cudaFuncSetAttribute(gemm_bf16, cudaFuncAttributeMaxDynamicSharedMemorySize,
                         GEMM_SMEM);

    const float qscale = 0.28867513459481287f;  // 1/sqrt(12)

    split_weights<<<WELTS / 256, 256>>>((const float*)d_in[2], (const float*)d_in[4],
                                        (const float*)d_in[6], (const float*)d_in[8]);
    split_x<<<NROWS * DD / 4 / 256, 256>>>(x);

    // Fused QKV: 9 n-blocks (3 segs x 3 cols), n fast for L2 reuse of A rows
    GemmArgs qkv;
    qkv.plane[0] = 0; qkv.plane[1] = 2; qkv.plane[2] = 4;
    qkv.bias[0] = bq; qkv.bias[1] = bk; qkv.bias[2] = bv;
    qkv.out[0] = pq;  qkv.out[1] = pk;  qkv.out[2] = pv;
    qkv.scale[0] = qscale; qkv.scale[1] = 1.f; qkv.scale[2] = 1.f;
    qkv.res = nullptr;
    dim3 qkv_grid(3 * DD / BN, NROWS / BM);     // (9, 1024)
    gemm_bf16<<<qkv_grid, 256, GEMM_SMEM>>>(pxs, qkv);

    band_attn<<<BATCH * (SEQ / TS), 256>>>(mask0);

    // Output projection + residual -> g_q (becomes h)
    GemmArgs og;
    og.plane[0] = 6; og.plane[1] = 6; og.plane[2] = 6;
    og.bias[0] = bo; og.bias[1] = bo; og.bias[2] = bo;
    og.out[0] = pq; og.out[1] = pq; og.out[2] = pq;
    og.scale[0] = 1.f; og.scale[1] = 1.f; og.scale[2] = 1.f;
    og.res = x;
    dim3 o_grid(DD / BN, NROWS / BM);           // (3, 1024)
    gemm_bf16<<<o_grid, 256, GEMM_SMEM>>>(pcs, og);

    layernorm<<<NROWS / 8, 256>>>(ln_g, ln_b, out);
}

// round 10
// speedup vs baseline: 1.0989x; 1.0989x over previous
#include <cuda_runtime.h>
#include <cuda_bf16.h>
#include <math.h>
#include <stdint.h>

// Problem dims (fixed by the dataset)
#define DD    192
#define HDIM  12
#define SEQ   8192
#define BATCH 16
#define NROWS (BATCH * SEQ)
#define WELTS (DD * DD)         // 36864 elements per weight
#define APLANE ((size_t)NROWS * DD)

// ---------------- scratch (static device globals) -------------------------
__device__ float g_q[(size_t)NROWS * DD];
__device__ float g_k[(size_t)NROWS * DD];
__device__ float g_v[(size_t)NROWS * DD];
// bf16 hi/lo planes (plane 0 = hi at offset 0, plane 1 = lo at +APLANE)
__device__ __nv_bfloat16 g_xsplit[(size_t)2 * NROWS * DD];
__device__ __nv_bfloat16 g_ctxsplit[(size_t)2 * NROWS * DD];
// bf16 hi/lo planes for Wq,Wk,Wv,Wo: plane index = w*2 + (0=hi,1=lo)
__device__ __nv_bfloat16 g_wsplit[(size_t)8 * WELTS];

// ---------------- helpers --------------------------------------------------
__device__ __forceinline__ uint32_t pack_bf2(__nv_bfloat16 a, __nv_bfloat16 b) {
    return (uint32_t)__bfloat16_as_ushort(a) |
           ((uint32_t)__bfloat16_as_ushort(b) << 16);
}
__device__ __forceinline__ void split2(float x, __nv_bfloat16& hi, __nv_bfloat16& lo) {
    hi = __float2bfloat16(x);
    lo = __float2bfloat16(x - __bfloat162float(hi));
}

// bf16 m16n8k16 mma, fp32 accumulate
__device__ __forceinline__ void mma16(float* c, const uint32_t* a, const uint32_t* b) {
    asm volatile(
        "mma.sync.aligned.m16n8k16.row.col.f32.bf16.bf16.f32 "
        "{%0,%1,%2,%3}, {%4,%5,%6,%7}, {%8,%9}, {%0,%1,%2,%3};"
        : "+f"(c[0]), "+f"(c[1]), "+f"(c[2]), "+f"(c[3])
        : "r"(a[0]), "r"(a[1]), "r"(a[2]), "r"(a[3]), "r"(b[0]), "r"(b[1]));
}

// 16-byte async copy global -> shared
__device__ __forceinline__ void cp_async16(uint32_t smem_dst, const void* gsrc) {
    asm volatile("cp.async.ca.shared.global [%0], [%1], 16;"
                 :: "r"(smem_dst), "l"(gsrc));
}

// ---------------- prep: split weights / activations ------------------------
__global__ __launch_bounds__(256)
void split_weights(const float* __restrict__ Wq, const float* __restrict__ Wk,
                   const float* __restrict__ Wv, const float* __restrict__ Wo)
{
    int f = blockIdx.x * 256 + threadIdx.x;     // float4 index
    int w  = f / (WELTS / 4);
    int e4 = (f - w * (WELTS / 4)) * 4;
    const float* W = (w == 0) ? Wq : (w == 1) ? Wk : (w == 2) ? Wv : Wo;
    float4 a = *(const float4*)&W[e4];
    __nv_bfloat16 h0,h1,h2,h3,l0,l1,l2,l3;
    split2(a.x,h0,l0); split2(a.y,h1,l1); split2(a.z,h2,l2); split2(a.w,h3,l3);
    uint2 hp, lp;
    hp.x = pack_bf2(h0,h1); hp.y = pack_bf2(h2,h3);
    lp.x = pack_bf2(l0,l1); lp.y = pack_bf2(l2,l3);
    *(uint2*)&g_wsplit[(size_t)(w*2)   * WELTS + e4] = hp;
    *(uint2*)&g_wsplit[(size_t)(w*2+1) * WELTS + e4] = lp;
}

__global__ __launch_bounds__(256)
void split_x(const float* __restrict__ x)
{
    size_t f = (size_t)blockIdx.x * 256 + threadIdx.x;   // float4 index
    float4 a = ((const float4*)x)[f];
    __nv_bfloat16 h0,h1,h2,h3,l0,l1,l2,l3;
    split2(a.x,h0,l0); split2(a.y,h1,l1); split2(a.z,h2,l2); split2(a.w,h3,l3);
    uint2 hp, lp;
    hp.x = pack_bf2(h0,h1); hp.y = pack_bf2(h2,h3);
    lp.x = pack_bf2(l0,l1); lp.y = pack_bf2(l2,l3);
    ((uint2*)g_xsplit)[f] = hp;
    ((uint2*)(g_xsplit + APLANE))[f] = lp;
}

// ---------------- GEMM: bf16 3-split, cp.async double-buffered -------------
// out[seg][r, c] = (sum_k A[r,k] * W[seg][c,k] + bias[seg][c]) * scale[seg]
//                  (+ res[r,c] if res)  where seg = blockIdx.x / 3.
#define BM 128
#define BN 64
#define BK 32
#define PADW 20                    // uint32 (bf16-pair) row stride
#define SM_AH 0
#define SM_AL (BM * PADW)          // 2560
#define SM_BH (2 * BM * PADW)      // 5120
#define SM_BL (2 * BM * PADW + BN * PADW)
#define BUFW  (2 * BM * PADW + 2 * BN * PADW)   // 7680 uint32 per buffer
#define GEMM_SMEM (2 * BUFW * 4)                // 61440 bytes

struct GemmArgs {
    int          plane[3];  // hi plane index in g_wsplit (lo = +1)
    const float* bias[3];
    float*       out[3];
    float        scale[3];
    const float* res;
};

__global__ __launch_bounds__(256, 3)
void gemm_bf16(const __nv_bfloat16* __restrict__ Abase, GemmArgs args)
{
    extern __shared__ uint32_t smem[];          // 2 * BUFW

    const int col0g = blockIdx.x * BN;
    const int seg   = col0g / DD;
    const int lc0   = col0g - seg * DD;
    const int row0  = blockIdx.y * BM;

    const uint4* __restrict__ A4 = (const uint4*)Abase;            // 24 uint4/row
    const uint4* __restrict__ W4 =
        (const uint4*)(g_wsplit + (size_t)args.plane[seg] * WELTS);

    const uint32_t smem_u32 =
        (uint32_t)__cvta_generic_to_shared(smem);

    const int tid  = threadIdx.x;
    const int lane = tid & 31;
    const int warp = tid >> 5;
    const int wm   = (warp & 3) * 32;   // 4 warps in m
    const int wn   = (warp >> 2) * 32;  // 2 warps in n
    const int g    = lane >> 2;
    const int t    = lane & 3;

    float acc[2][4][4];
    #pragma unroll
    for (int i = 0; i < 2; i++)
        #pragma unroll
        for (int j = 0; j < 4; j++)
            #pragma unroll
            for (int c = 0; c < 4; c++) acc[i][j][c] = 0.f;

    // ---- async staging: no registers held across compute -------------------
    // Per chunk: A = 1024 uint4 (2 planes x 128 rows x 4), B = 512 uint4.
    auto stage_async = [&](int c, int buf) {
        uint32_t base = smem_u32 + (uint32_t)buf * (BUFW * 4);
        #pragma unroll
        for (int i = 0; i < 4; i++) {
            int idx = tid + i * 256;
            int pl = idx >> 9, rem = idx & 511;
            int m = rem >> 2, q4 = rem & 3;
            const uint4* src =
                &A4[(size_t)pl * (APLANE / 8) + (size_t)(row0 + m) * 24 + c * 4 + q4];
            uint32_t dst = base +
                (uint32_t)((pl ? SM_AL : SM_AH) + m * PADW + q4 * 4) * 4;
            cp_async16(dst, src);
        }
        #pragma unroll
        for (int i = 0; i < 2; i++) {
            int idx = tid + i * 256;
            int pl = idx >> 8, rem = idx & 255;
            int n = rem >> 2, q4 = rem & 3;
            const uint4* src =
                &W4[(size_t)pl * (WELTS / 8) + (size_t)(lc0 + n) * 24 + c * 4 + q4];
            uint32_t dst = base +
                (uint32_t)((pl ? SM_BL : SM_BH) + n * PADW + q4 * 4) * 4;
            cp_async16(dst, src);
        }
        asm volatile("cp.async.commit_group;" ::: "memory");
    };

    // ---- prologue: prefetch chunk 0 ----------------------------------------
    stage_async(0, 0);

    // ---- pipelined main loop over 6 chunks ---------------------------------
    #pragma unroll
    for (int c = 0; c < 6; c++) {
        uint32_t* cur = smem + (c & 1) * BUFW;

        if (c < 5) {
            stage_async(c + 1, (c + 1) & 1);
            asm volatile("cp.async.wait_group 1;" ::: "memory");  // chunk c done
        } else {
            asm volatile("cp.async.wait_group 0;" ::: "memory");
        }
        __syncthreads();   // chunk c data visible to all warps

        #pragma unroll
        for (int ks = 0; ks < 2; ks++) {
            const int kpb = ks * 8;
            uint32_t ah[2][4], al[2][4];
            #pragma unroll
            for (int mt = 0; mt < 2; mt++) {
                int o = (wm + mt * 16 + g) * PADW + kpb + t;
                ah[mt][0] = cur[SM_AH + o];
                ah[mt][1] = cur[SM_AH + o + 8 * PADW];
                ah[mt][2] = cur[SM_AH + o + 4];
                ah[mt][3] = cur[SM_AH + o + 8 * PADW + 4];
                al[mt][0] = cur[SM_AL + o];
                al[mt][1] = cur[SM_AL + o + 8 * PADW];
                al[mt][2] = cur[SM_AL + o + 4];
                al[mt][3] = cur[SM_AL + o + 8 * PADW + 4];
            }
            uint32_t bh[4][2], bl[4][2];
            #pragma unroll
            for (int nt = 0; nt < 4; nt++) {
                int o = (wn + nt * 8 + g) * PADW + kpb + t;
                bh[nt][0] = cur[SM_BH + o];
                bh[nt][1] = cur[SM_BH + o + 4];
                bl[nt][0] = cur[SM_BL + o];
                bl[nt][1] = cur[SM_BL + o + 4];
            }
            // interleaved ordering (R6-proven): per-acc chain al*bh, ah*bl, ah*bh
            #pragma unroll
            for (int mt = 0; mt < 2; mt++)
                #pragma unroll
                for (int nt = 0; nt < 4; nt++) {
                    mma16(acc[mt][nt], al[mt], bh[nt]);
                    mma16(acc[mt][nt], ah[mt], bl[nt]);
                    mma16(acc[mt][nt], ah[mt], bh[nt]);
                }
        }
        __syncthreads();   // all warps done reading buf (overwritten at c+2)
    }

    // ---- epilogue ----------------------------------------------------------
    const float scale = args.scale[seg];
    float* const outp = args.out[seg];
    const float* const bias = args.bias[seg];
    const float* const res  = args.res;

    #pragma unroll
    for (int mt = 0; mt < 2; mt++) {
        #pragma unroll
        for (int nt = 0; nt < 4; nt++) {
            int row = row0 + wm + mt * 16 + g;
            int col = lc0 + wn + nt * 8 + t * 2;
            float b0 = bias[col], b1 = bias[col + 1];
            #pragma unroll
            for (int half = 0; half < 2; half++) {
                int r = row + half * 8;
                float v0 = (acc[mt][nt][half * 2 + 0] + b0) * scale;
                float v1 = (acc[mt][nt][half * 2 + 1] + b1) * scale;
                if (res != nullptr) {
                    const float2 rv = *(const float2*)&res[(size_t)r * DD + col];
                    v0 += rv.x; v1 += rv.y;
                }
                float2 o; o.x = v0; o.y = v1;
                *(float2*)&outp[(size_t)r * DD + col] = o;
            }
        }
    }
}

// ---------------- banded attention: window d in [-2, 2] --------------------
#define TS 16
#define KVROWS (TS + 4)

__global__ __launch_bounds__(256)
void band_attn(const float* __restrict__ mask0)
{
    __shared__ float ks[KVROWS * DD];
    __shared__ float vs[KVROWS * DD];
    __shared__ float msk[KVROWS];

    const int chunk = blockIdx.x;
    const int b  = chunk / (SEQ / TS);
    const int s0 = (chunk % (SEQ / TS)) * TS;
    const int tid = threadIdx.x;

    for (int i4 = tid; i4 < KVROWS * (DD / 4); i4 += 256) {
        int r  = i4 / (DD / 4);
        int c4 = i4 % (DD / 4);
        int s  = s0 - 2 + r;
        float4 kv = make_float4(0.f, 0.f, 0.f, 0.f);
        float4 vv = make_float4(0.f, 0.f, 0.f, 0.f);
        if (s >= 0 && s < SEQ) {
            size_t off = (size_t)(b * SEQ + s) * DD + c4 * 4;
            kv = *(const float4*)&g_k[off];
            vv = *(const float4*)&g_v[off];
        }
        *(float4*)&ks[r * DD + c4 * 4] = kv;
        *(float4*)&vs[r * DD + c4 * 4] = vv;
    }
    if (tid < KVROWS) {
        int s = s0 - 2 + tid;
        msk[tid] = (s >= 0 && s < SEQ) ? mask0[b * SEQ + s] : 0.f;
    }
    __syncthreads();

    const int sl = tid >> 4;
    const int h  = tid & 15;
    const int s  = s0 + sl;

    float q[HDIM];
    {
        const float* qp = &g_q[(size_t)(b * SEQ + s) * DD + h * HDIM];
        float4 q0 = *(const float4*)(qp + 0);
        float4 q1 = *(const float4*)(qp + 4);
        float4 q2 = *(const float4*)(qp + 8);
        q[0]=q0.x; q[1]=q0.y; q[2]=q0.z;  q[3]=q0.w;
        q[4]=q1.x; q[5]=q1.y; q[6]=q1.z;  q[7]=q1.w;
        q[8]=q2.x; q[9]=q2.y; q[10]=q2.z; q[11]=q2.w;
    }

    const float NEG  = -3.402823466e38f;
    const float NINF = __int_as_float(0xff800000);

    float sc[5];
    #pragma unroll
    for (int d = 0; d < 5; d++) {
        int r = sl + d;
        int skey = s + d - 2;
        const float* kp = &ks[r * DD + h * HDIM];
        float dot = 0.f;
        #pragma unroll
        for (int j = 0; j < HDIM; j++) dot += q[j] * kp[j];
        float fm = (msk[r] != 0.f) ? NEG : 0.f;
        sc[d] = (skey >= 0 && skey < SEQ) ? (dot + fm) : NINF;
    }

    float mx = sc[0];
    #pragma unroll
    for (int d = 1; d < 5; d++) mx = fmaxf(mx, sc[d]);
    float e[5], sum = 0.f;
    #pragma unroll
    for (int d = 0; d < 5; d++) { e[d] = expf(sc[d] - mx); sum += e[d]; }
    float inv = 1.f / sum;
    bool index_masked = (msk[sl + 2] < 0.f);

    float c[HDIM] = {};
    #pragma unroll
    for (int d = 0; d < 5; d++) {
        float p = index_masked ? 0.f : e[d] * inv;
        const float* vp = &vs[(sl + d) * DD + h * HDIM];
        #pragma unroll
        for (int j = 0; j < HDIM; j++) c[j] += p * vp[j];
    }

    // write ctx directly as bf16 hi/lo planes for the O-projection
    // HDIM = 12 bf16 values = 6 packed uint32 per plane
    __nv_bfloat16 chi[HDIM], clo[HDIM];
    #pragma unroll
    for (int j = 0; j < HDIM; j++) split2(c[j], chi[j], clo[j]);
    size_t base = (size_t)(b * SEQ + s) * DD + h * HDIM;
    uint32_t* oh = (uint32_t*)(g_ctxsplit + base);
    uint32_t* ol = (uint32_t*)(g_ctxsplit + APLANE + base);
    #pragma unroll
    for (int j = 0; j < 6; j++) {
        oh[j] = pack_bf2(chi[2*j], chi[2*j+1]);
        ol[j] = pack_bf2(clo[2*j], clo[2*j+1]);
    }
}

// ---------------- LayerNorm over the last dim (192), warp per row ----------
__global__ __launch_bounds__(256)
void layernorm(const float* __restrict__ ln_g, const float* __restrict__ ln_b,
               float* __restrict__ out)
{
    const int row  = blockIdx.x * 8 + (threadIdx.x >> 5);
    const int lane = threadIdx.x & 31;

    const float* hp = &g_q[(size_t)row * DD];  // g_q holds h after O-proj
    float h[6];
    float sum = 0.f;
    #pragma unroll
    for (int j = 0; j < 6; j++) { h[j] = hp[lane + j * 32]; sum += h[j]; }
    #pragma unroll
    for (int o = 16; o > 0; o >>= 1) sum += __shfl_xor_sync(0xffffffffu, sum, o);
    float mu = sum * (1.f / 192.f);

    float s2 = 0.f;
    #pragma unroll
    for (int j = 0; j < 6; j++) { float d = h[j] - mu; s2 += d * d; }
    #pragma unroll
    for (int o = 16; o > 0; o >>= 1) s2 += __shfl_xor_sync(0xffffffffu, s2, o);
    float invstd = rsqrtf(s2 * (1.f / 192.f) + 1e-12f);

    float* op = &out[(size_t)row * DD];
    #pragma unroll
    for (int j = 0; j < 6; j++) {
        int cc = lane + j * 32;
        op[cc] = (h[j] - mu) * invstd * ln_g[cc] + ln_b[cc];
    }
}

// ---------------- launch ---------------------------------------------------
extern "C" void kernel_launch(void* const* d_in, const int* in_sizes, int n_in,
                              void* d_out, int out_size)
{
    const float* x     = (const float*)d_in[0];
    const float* mask0 = (const float*)d_in[1];
    const float* bq    = (const float*)d_in[3];
    const float* bk    = (const float*)d_in[5];
    const float* bv    = (const float*)d_in[7];
    const float* bo    = (const float*)d_in[9];
    const float* ln_g  = (const float*)d_in[10];
    const float* ln_b  = (const float*)d_in[11];
    float* out = (float*)d_out;

    float *pq, *pk, *pv;
    __nv_bfloat16 *pxs, *pcs;
    cudaGetSymbolAddress((void**)&pq,  g_q);
    cudaGetSymbolAddress((void**)&pk,  g_k);
    cudaGetSymbolAddress((void**)&pv,  g_v);
    cudaGetSymbolAddress((void**)&pxs, g_xsplit);
    cudaGetSymbolAddress((void**)&pcs, g_ctxsplit);

    cudaFuncSetAttribute(gemm_bf16, cudaFuncAttributeMaxDynamicSharedMemorySize,
                         GEMM_SMEM);

    const float qscale = 0.28867513459481287f;  // 1/sqrt(12)

    split_weights<<<WELTS / 256, 256>>>((const float*)d_in[2], (const float*)d_in[4],
                                        (const float*)d_in[6], (const float*)d_in[8]);
    split_x<<<NROWS * DD / 4 / 256, 256>>>(x);

    // Fused QKV: 9 n-blocks (3 segs x 3 cols), n fast for L2 reuse of A rows
    GemmArgs qkv;
    qkv.plane[0] = 0; qkv.plane[1] = 2; qkv.plane[2] = 4;
    qkv.bias[0] = bq; qkv.bias[1] = bk; qkv.bias[2] = bv;
    qkv.out[0] = pq;  qkv.out[1] = pk;  qkv.out[2] = pv;
    qkv.scale[0] = qscale; qkv.scale[1] = 1.f; qkv.scale[2] = 1.f;
    qkv.res = nullptr;
    dim3 qkv_grid(3 * DD / BN, NROWS / BM);     // (9, 1024)
    gemm_bf16<<<qkv_grid, 256, GEMM_SMEM>>>(pxs, qkv);

    band_attn<<<BATCH * (SEQ / TS), 256>>>(mask0);

    // Output projection + residual -> g_q (becomes h)
    GemmArgs og;
    og.plane[0] = 6; og.plane[1] = 6; og.plane[2] = 6;
    og.bias[0] = bo; og.bias[1] = bo; og.bias[2] = bo;
    og.out[0] = pq; og.out[1] = pq; og.out[2] = pq;
    og.scale[0] = 1.f; og.scale[1] = 1.f; og.scale[2] = 1.f;
    og.res = x;
    dim3 o_grid(DD / BN, NROWS / BM);           // (3, 1024)
    gemm_bf16<<<o_grid, 256, GEMM_SMEM>>>(pcs, og);

    layernorm<<<NROWS / 8, 256>>>(ln_g, ln_b, out);
}

// round 12
// speedup vs baseline: 1.5139x; 1.3777x over previous
#include <cuda_runtime.h>
#include <cuda_bf16.h>
#include <math.h>
#include <stdint.h>

// Problem dims (fixed by the dataset)
#define DD    192
#define HDIM  12
#define SEQ   8192
#define BATCH 16
#define NROWS (BATCH * SEQ)
#define WELTS (DD * DD)         // 36864 elements per weight
#define APLANE ((size_t)NROWS * DD)

// ---------------- scratch (static device globals) -------------------------
__device__ float g_q[(size_t)NROWS * DD];
__device__ float g_k[(size_t)NROWS * DD];
__device__ float g_v[(size_t)NROWS * DD];
// bf16 hi/lo planes (plane 0 = hi at offset 0, plane 1 = lo at +APLANE)
__device__ __nv_bfloat16 g_xsplit[(size_t)2 * NROWS * DD];
__device__ __nv_bfloat16 g_ctxsplit[(size_t)2 * NROWS * DD];
// bf16 hi/lo planes for Wq,Wk,Wv,Wo: plane index = w*2 + (0=hi,1=lo)
__device__ __nv_bfloat16 g_wsplit[(size_t)8 * WELTS];

// ---------------- helpers --------------------------------------------------
__device__ __forceinline__ uint32_t pack_bf2(__nv_bfloat16 a, __nv_bfloat16 b) {
    return (uint32_t)__bfloat16_as_ushort(a) |
           ((uint32_t)__bfloat16_as_ushort(b) << 16);
}
__device__ __forceinline__ void split2(float x, __nv_bfloat16& hi, __nv_bfloat16& lo) {
    hi = __float2bfloat16(x);
    lo = __float2bfloat16(x - __bfloat162float(hi));
}

// bf16 m16n8k16 mma, fp32 accumulate
__device__ __forceinline__ void mma16(float* c, const uint32_t* a, const uint32_t* b) {
    asm volatile(
        "mma.sync.aligned.m16n8k16.row.col.f32.bf16.bf16.f32 "
        "{%0,%1,%2,%3}, {%4,%5,%6,%7}, {%8,%9}, {%0,%1,%2,%3};"
        : "+f"(c[0]), "+f"(c[1]), "+f"(c[2]), "+f"(c[3])
        : "r"(a[0]), "r"(a[1]), "r"(a[2]), "r"(a[3]), "r"(b[0]), "r"(b[1]));
}

// ldmatrix: 4x 8x8 b16 tiles, per-lane addresses
__device__ __forceinline__ void ldsm4(uint32_t& r0, uint32_t& r1,
                                      uint32_t& r2, uint32_t& r3, uint32_t addr) {
    asm volatile("ldmatrix.sync.aligned.m8n8.x4.shared.b16 {%0,%1,%2,%3}, [%4];"
                 : "=r"(r0), "=r"(r1), "=r"(r2), "=r"(r3) : "r"(addr));
}

// ---------------- prep: split weights / activations ------------------------
__global__ __launch_bounds__(256)
void split_weights(const float* __restrict__ Wq, const float* __restrict__ Wk,
                   const float* __restrict__ Wv, const float* __restrict__ Wo)
{
    int f = blockIdx.x * 256 + threadIdx.x;     // float4 index
    int w  = f / (WELTS / 4);
    int e4 = (f - w * (WELTS / 4)) * 4;
    const float* W = (w == 0) ? Wq : (w == 1) ? Wk : (w == 2) ? Wv : Wo;
    float4 a = *(const float4*)&W[e4];
    __nv_bfloat16 h0,h1,h2,h3,l0,l1,l2,l3;
    split2(a.x,h0,l0); split2(a.y,h1,l1); split2(a.z,h2,l2); split2(a.w,h3,l3);
    uint2 hp, lp;
    hp.x = pack_bf2(h0,h1); hp.y = pack_bf2(h2,h3);
    lp.x = pack_bf2(l0,l1); lp.y = pack_bf2(l2,l3);
    *(uint2*)&g_wsplit[(size_t)(w*2)   * WELTS + e4] = hp;
    *(uint2*)&g_wsplit[(size_t)(w*2+1) * WELTS + e4] = lp;
}

__global__ __launch_bounds__(256)
void split_x(const float* __restrict__ x)
{
    size_t f = (size_t)blockIdx.x * 256 + threadIdx.x;   // float4 index
    float4 a = ((const float4*)x)[f];
    __nv_bfloat16 h0,h1,h2,h3,l0,l1,l2,l3;
    split2(a.x,h0,l0); split2(a.y,h1,l1); split2(a.z,h2,l2); split2(a.w,h3,l3);
    uint2 hp, lp;
    hp.x = pack_bf2(h0,h1); hp.y = pack_bf2(h2,h3);
    lp.x = pack_bf2(l0,l1); lp.y = pack_bf2(l2,l3);
    ((uint2*)g_xsplit)[f] = hp;
    ((uint2*)(g_xsplit + APLANE))[f] = lp;
}

// ---------------- GEMM: bf16 3-split, double-buffered pipeline -------------
// out[seg][r, c] = (sum_k A[r,k] * W[seg][c,k] + bias[seg][c]) * scale[seg]
//                  (+ res[r,c] if res)  where seg = blockIdx.x / 3.
#define BM 128
#define BN 64
#define BK 32
#define PADW 20                    // uint32 (bf16-pair) row stride
#define SM_AH 0
#define SM_AL (BM * PADW)          // 2560
#define SM_BH (2 * BM * PADW)      // 5120
#define SM_BL (2 * BM * PADW + BN * PADW)
#define BUFW  (2 * BM * PADW + 2 * BN * PADW)   // 7680 uint32 per buffer
#define GEMM_SMEM (2 * BUFW * 4)                // 61440 bytes

struct GemmArgs {
    int          plane[3];  // hi plane index in g_wsplit (lo = +1)
    const float* bias[3];
    float*       out[3];
    float        scale[3];
    const float* res;
};

__global__ __launch_bounds__(256, 2)
void gemm_bf16(const __nv_bfloat16* __restrict__ Abase, GemmArgs args)
{
    extern __shared__ uint32_t smem[];          // 2 * BUFW

    const int col0g = blockIdx.x * BN;
    const int seg   = col0g / DD;
    const int lc0   = col0g - seg * DD;
    const int row0  = blockIdx.y * BM;

    const uint4* __restrict__ A4 = (const uint4*)Abase;            // 24 uint4/row
    const uint4* __restrict__ W4 =
        (const uint4*)(g_wsplit + (size_t)args.plane[seg] * WELTS);

    const int tid  = threadIdx.x;
    const int lane = tid & 31;
    const int warp = tid >> 5;
    const int wm   = (warp & 3) * 32;   // 4 warps in m
    const int wn   = (warp >> 2) * 32;  // 2 warps in n
    const int g    = lane >> 2;
    const int t    = lane & 3;

    const uint32_t smem_base = (uint32_t)__cvta_generic_to_shared(smem);

    // per-lane ldmatrix geometry (word units; x4 tile order matches scalar map)
    // A tiles: (row g, kp t), (row g+8, kp t), (row g, kp t+4), (row g+8, kp t+4)
    const int arow  = wm + (lane & 15);          // lanes 0-15 rows, 16-31 same rows
    const int aksel = (lane >> 4) * 4;           // second half: kpair +4
    // B tiles: (n g, kp t), (n g, kp t+4), (n+8 g, kp t), (n+8 g, kp t+4)
    const int brow  = wn + (lane & 7) + ((lane >> 4) << 3);
    const int bksel = ((lane >> 3) & 1) * 4;

    float acc[2][4][4];
    #pragma unroll
    for (int i = 0; i < 2; i++)
        #pragma unroll
        for (int j = 0; j < 4; j++)
            #pragma unroll
            for (int c = 0; c < 4; c++) acc[i][j][c] = 0.f;

    // ---- staging helpers (pure copies; planes pre-converted) --------------
    auto load_chunk = [&](int c, uint4* na, uint4* nb) {
        #pragma unroll
        for (int i = 0; i < 4; i++) {
            int idx = tid + i * 256;
            int pl = idx >> 9, rem = idx & 511;
            int m = rem >> 2, q4 = rem & 3;
            na[i] = A4[(size_t)pl * (APLANE / 8) + (size_t)(row0 + m) * 24 + c * 4 + q4];
        }
        #pragma unroll
        for (int i = 0; i < 2; i++) {
            int idx = tid + i * 256;
            int pl = idx >> 8, rem = idx & 255;
            int n = rem >> 2, q4 = rem & 3;
            nb[i] = W4[(size_t)pl * (WELTS / 8) + (size_t)(lc0 + n) * 24 + c * 4 + q4];
        }
    };
    auto store_chunk = [&](uint32_t* buf, const uint4* na, const uint4* nb) {
        #pragma unroll
        for (int i = 0; i < 4; i++) {
            int idx = tid + i * 256;
            int pl = idx >> 9, rem = idx & 511;
            int m = rem >> 2, q4 = rem & 3;
            *(uint4*)&buf[(pl ? SM_AL : SM_AH) + m * PADW + q4 * 4] = na[i];
        }
        #pragma unroll
        for (int i = 0; i < 2; i++) {
            int idx = tid + i * 256;
            int pl = idx >> 8, rem = idx & 255;
            int n = rem >> 2, q4 = rem & 3;
            *(uint4*)&buf[(pl ? SM_BL : SM_BH) + n * PADW + q4 * 4] = nb[i];
        }
    };

    // ---- prologue ----------------------------------------------------------
    {
        uint4 pa[4], pb[2];
        load_chunk(0, pa, pb);
        store_chunk(smem, pa, pb);
    }
    __syncthreads();

    // ---- pipelined main loop over 6 chunks ---------------------------------
    #pragma unroll
    for (int c = 0; c < 6; c++) {
        uint32_t* cur = smem + (c & 1) * BUFW;
        uint32_t* nxt = smem + ((c + 1) & 1) * BUFW;
        const uint32_t bufb = smem_base + (uint32_t)((c & 1) * BUFW) * 4;
        uint4 na[4], nb[2];
        if (c < 5) load_chunk(c + 1, na, nb);

        #pragma unroll
        for (int ks = 0; ks < 2; ks++) {
            const int kpb = ks * 8;
            uint32_t ah[2][4], al[2][4];
            #pragma unroll
            for (int mt = 0; mt < 2; mt++) {
                uint32_t aaddr = bufb +
                    (uint32_t)(SM_AH + (arow + mt * 16) * PADW + kpb + aksel) * 4;
                ldsm4(ah[mt][0], ah[mt][1], ah[mt][2], ah[mt][3], aaddr);
                ldsm4(al[mt][0], al[mt][1], al[mt][2], al[mt][3],
                      aaddr + (uint32_t)(SM_AL - SM_AH) * 4);
            }
            uint32_t bh[4][2], bl[4][2];
            #pragma unroll
            for (int p = 0; p < 2; p++) {
                uint32_t baddr = bufb +
                    (uint32_t)(SM_BH + (brow + p * 16) * PADW + kpb + bksel) * 4;
                ldsm4(bh[2*p][0], bh[2*p][1], bh[2*p+1][0], bh[2*p+1][1], baddr);
                ldsm4(bl[2*p][0], bl[2*p][1], bl[2*p+1][0], bl[2*p+1][1],
                      baddr + (uint32_t)(SM_BL - SM_BH) * 4);
            }
            // interleaved ordering (R8-proven): per-acc chain al*bh, ah*bl, ah*bh
            #pragma unroll
            for (int mt = 0; mt < 2; mt++)
                #pragma unroll
                for (int nt = 0; nt < 4; nt++) {
                    mma16(acc[mt][nt], al[mt], bh[nt]);
                    mma16(acc[mt][nt], ah[mt], bl[nt]);
                    mma16(acc[mt][nt], ah[mt], bh[nt]);
                }
        }

        if (c < 5) store_chunk(nxt, na, nb);
        __syncthreads();
    }

    // ---- epilogue ----------------------------------------------------------
    const float scale = args.scale[seg];
    float* const outp = args.out[seg];
    const float* const bias = args.bias[seg];
    const float* const res  = args.res;

    #pragma unroll
    for (int mt = 0; mt < 2; mt++) {
        #pragma unroll
        for (int nt = 0; nt < 4; nt++) {
            int row = row0 + wm + mt * 16 + g;
            int col = lc0 + wn + nt * 8 + t * 2;
            float b0 = bias[col], b1 = bias[col + 1];
            #pragma unroll
            for (int half = 0; half < 2; half++) {
                int r = row + half * 8;
                float v0 = (acc[mt][nt][half * 2 + 0] + b0) * scale;
                float v1 = (acc[mt][nt][half * 2 + 1] + b1) * scale;
                if (res != nullptr) {
                    const float2 rv = *(const float2*)&res[(size_t)r * DD + col];
                    v0 += rv.x; v1 += rv.y;
                }
                float2 o; o.x = v0; o.y = v1;
                *(float2*)&outp[(size_t)r * DD + col] = o;
            }
        }
    }
}

// ---------------- banded attention: window d in [-2, 2] --------------------
#define TS 16
#define KVROWS (TS + 4)

__global__ __launch_bounds__(256)
void band_attn(const float* __restrict__ mask0)
{
    __shared__ float ks[KVROWS * DD];
    __shared__ float vs[KVROWS * DD];
    __shared__ float msk[KVROWS];

    const int chunk = blockIdx.x;
    const int b  = chunk / (SEQ / TS);
    const int s0 = (chunk % (SEQ / TS)) * TS;
    const int tid = threadIdx.x;

    for (int i4 = tid; i4 < KVROWS * (DD / 4); i4 += 256) {
        int r  = i4 / (DD / 4);
        int c4 = i4 % (DD / 4);
        int s  = s0 - 2 + r;
        float4 kv = make_float4(0.f, 0.f, 0.f, 0.f);
        float4 vv = make_float4(0.f, 0.f, 0.f, 0.f);
        if (s >= 0 && s < SEQ) {
            size_t off = (size_t)(b * SEQ + s) * DD + c4 * 4;
            kv = *(const float4*)&g_k[off];
            vv = *(const float4*)&g_v[off];
        }
        *(float4*)&ks[r * DD + c4 * 4] = kv;
        *(float4*)&vs[r * DD + c4 * 4] = vv;
    }
    if (tid < KVROWS) {
        int s = s0 - 2 + tid;
        msk[tid] = (s >= 0 && s < SEQ) ? mask0[b * SEQ + s] : 0.f;
    }
    __syncthreads();

    const int sl = tid >> 4;
    const int h  = tid & 15;
    const int s  = s0 + sl;

    float q[HDIM];
    {
        const float* qp = &g_q[(size_t)(b * SEQ + s) * DD + h * HDIM];
        float4 q0 = *(const float4*)(qp + 0);
        float4 q1 = *(const float4*)(qp + 4);
        float4 q2 = *(const float4*)(qp + 8);
        q[0]=q0.x; q[1]=q0.y; q[2]=q0.z;  q[3]=q0.w;
        q[4]=q1.x; q[5]=q1.y; q[6]=q1.z;  q[7]=q1.w;
        q[8]=q2.x; q[9]=q2.y; q[10]=q2.z; q[11]=q2.w;
    }

    const float NEG  = -3.402823466e38f;
    const float NINF = __int_as_float(0xff800000);

    float sc[5];
    #pragma unroll
    for (int d = 0; d < 5; d++) {
        int r = sl + d;
        int skey = s + d - 2;
        const float* kp = &ks[r * DD + h * HDIM];
        float dot = 0.f;
        #pragma unroll
        for (int j = 0; j < HDIM; j++) dot += q[j] * kp[j];
        float fm = (msk[r] != 0.f) ? NEG : 0.f;
        sc[d] = (skey >= 0 && skey < SEQ) ? (dot + fm) : NINF;
    }

    float mx = sc[0];
    #pragma unroll
    for (int d = 1; d < 5; d++) mx = fmaxf(mx, sc[d]);
    float e[5], sum = 0.f;
    #pragma unroll
    for (int d = 0; d < 5; d++) { e[d] = expf(sc[d] - mx); sum += e[d]; }
    float inv = 1.f / sum;
    bool index_masked = (msk[sl + 2] < 0.f);

    float c[HDIM] = {};
    #pragma unroll
    for (int d = 0; d < 5; d++) {
        float p = index_masked ? 0.f : e[d] * inv;
        const float* vp = &vs[(sl + d) * DD + h * HDIM];
        #pragma unroll
        for (int j = 0; j < HDIM; j++) c[j] += p * vp[j];
    }

    // write ctx directly as bf16 hi/lo planes for the O-projection
    // HDIM = 12 bf16 values = 6 packed uint32 per plane
    __nv_bfloat16 chi[HDIM], clo[HDIM];
    #pragma unroll
    for (int j = 0; j < HDIM; j++) split2(c[j], chi[j], clo[j]);
    size_t base = (size_t)(b * SEQ + s) * DD + h * HDIM;
    uint32_t* oh = (uint32_t*)(g_ctxsplit + base);
    uint32_t* ol = (uint32_t*)(g_ctxsplit + APLANE + base);
    #pragma unroll
    for (int j = 0; j < 6; j++) {
        oh[j] = pack_bf2(chi[2*j], chi[2*j+1]);
        ol[j] = pack_bf2(clo[2*j], clo[2*j+1]);
    }
}

// ---------------- LayerNorm over the last dim (192), warp per row ----------
__global__ __launch_bounds__(256)
void layernorm(const float* __restrict__ ln_g, const float* __restrict__ ln_b,
               float* __restrict__ out)
{
    const int row  = blockIdx.x * 8 + (threadIdx.x >> 5);
    const int lane = threadIdx.x & 31;

    const float* hp = &g_q[(size_t)row * DD];  // g_q holds h after O-proj
    float h[6];
    float sum = 0.f;
    #pragma unroll
    for (int j = 0; j < 6; j++) { h[j] = hp[lane + j * 32]; sum += h[j]; }
    #pragma unroll
    for (int o = 16; o > 0; o >>= 1) sum += __shfl_xor_sync(0xffffffffu, sum, o);
    float mu = sum * (1.f / 192.f);

    float s2 = 0.f;
    #pragma unroll
    for (int j = 0; j < 6; j++) { float d = h[j] - mu; s2 += d * d; }
    #pragma unroll
    for (int o = 16; o > 0; o >>= 1) s2 += __shfl_xor_sync(0xffffffffu, s2, o);
    float invstd = rsqrtf(s2 * (1.f / 192.f) + 1e-12f);

    float* op = &out[(size_t)row * DD];
    #pragma unroll
    for (int j = 0; j < 6; j++) {
        int cc = lane + j * 32;
        op[cc] = (h[j] - mu) * invstd * ln_g[cc] + ln_b[cc];
    }
}

// ---------------- launch ---------------------------------------------------
extern "C" void kernel_launch(void* const* d_in, const int* in_sizes, int n_in,
                              void* d_out, int out_size)
{
    const float* x     = (const float*)d_in[0];
    const float* mask0 = (const float*)d_in[1];
    const float* bq    = (const float*)d_in[3];
    const float* bk    = (const float*)d_in[5];
    const float* bv    = (const float*)d_in[7];
    const float* bo    = (const float*)d_in[9];
    const float* ln_g  = (const float*)d_in[10];
    const float* ln_b  = (const float*)d_in[11];
    float* out = (float*)d_out;

    float *pq, *pk, *pv;
    __nv_bfloat16 *pxs, *pcs;
    cudaGetSymbolAddress((void**)&pq,  g_q);
    cudaGetSymbolAddress((void**)&pk,  g_k);
    cudaGetSymbolAddress((void**)&pv,  g_v);
    cudaGetSymbolAddress((void**)&pxs, g_xsplit);
    cudaGetSymbolAddress((void**)&pcs, g_ctxsplit);

    cudaFuncSetAttribute(gemm_bf16, cudaFuncAttributeMaxDynamicSharedMemorySize,
                         GEMM_SMEM);

    const float qscale = 0.28867513459481287f;  // 1/sqrt(12)

    split_weights<<<WELTS / 256, 256>>>((const float*)d_in[2], (const float*)d_in[4],
                                        (const float*)d_in[6], (const float*)d_in[8]);
    split_x<<<NROWS * DD / 4 / 256, 256>>>(x);

    // Fused QKV: 9 n-blocks (3 segs x 3 cols), n fast for L2 reuse of A rows
    GemmArgs qkv;
    qkv.plane[0] = 0; qkv.plane[1] = 2; qkv.plane[2] = 4;
    qkv.bias[0] = bq; qkv.bias[1] = bk; qkv.bias[2] = bv;
    qkv.out[0] = pq;  qkv.out[1] = pk;  qkv.out[2] = pv;
    qkv.scale[0] = qscale; qkv.scale[1] = 1.f; qkv.scale[2] = 1.f;
    qkv.res = nullptr;
    dim3 qkv_grid(3 * DD / BN, NROWS / BM);     // (9, 1024)
    gemm_bf16<<<qkv_grid, 256, GEMM_SMEM>>>(pxs, qkv);

    band_attn<<<BATCH * (SEQ / TS), 256>>>(mask0);

    // Output projection + residual -> g_q (becomes h)
    GemmArgs og;
    og.plane[0] = 6; og.plane[1] = 6; og.plane[2] = 6;
    og.bias[0] = bo; og.bias[1] = bo; og.bias[2] = bo;
    og.out[0] = pq; og.out[1] = pq; og.out[2] = pq;
    og.scale[0] = 1.f; og.scale[1] = 1.f; og.scale[2] = 1.f;
    og.res = x;
    dim3 o_grid(DD / BN, NROWS / BM);           // (3, 1024)
    gemm_bf16<<<o_grid, 256, GEMM_SMEM>>>(pcs, og);

    layernorm<<<NROWS / 8, 256>>>(ln_g, ln_b, out);
}

// round 13
// speedup vs baseline: 2.3030x; 1.5212x over previous
#include <cuda_runtime.h>
#include <cuda_fp16.h>
#include <math.h>
#include <stdint.h>

// Problem dims (fixed by the dataset)
#define DD    192
#define HDIM  12
#define SEQ   8192
#define BATCH 16
#define NROWS (BATCH * SEQ)
#define WELTS (DD * DD)         // 36864 elements per weight

// ---------------- scratch (static device globals) -------------------------
__device__ float g_q[(size_t)NROWS * DD];
__device__ float g_k[(size_t)NROWS * DD];
__device__ float g_v[(size_t)NROWS * DD];
__device__ __half g_xh[(size_t)NROWS * DD];     // x as fp16
__device__ __half g_ctxh[(size_t)NROWS * DD];   // attention context as fp16
__device__ __half g_wh[(size_t)4 * WELTS];      // Wq,Wk,Wv,Wo as fp16

// ---------------- helpers --------------------------------------------------
__device__ __forceinline__ uint32_t pack_h2(__half a, __half b) {
    return (uint32_t)__half_as_ushort(a) | ((uint32_t)__half_as_ushort(b) << 16);
}

// fp16 m16n8k16 mma, fp32 accumulate
__device__ __forceinline__ void mma16(float* c, const uint32_t* a, const uint32_t* b) {
    asm volatile(
        "mma.sync.aligned.m16n8k16.row.col.f32.f16.f16.f32 "
        "{%0,%1,%2,%3}, {%4,%5,%6,%7}, {%8,%9}, {%0,%1,%2,%3};"
        : "+f"(c[0]), "+f"(c[1]), "+f"(c[2]), "+f"(c[3])
        : "r"(a[0]), "r"(a[1]), "r"(a[2]), "r"(a[3]), "r"(b[0]), "r"(b[1]));
}

// ldmatrix: 4x 8x8 b16 tiles, per-lane addresses
__device__ __forceinline__ void ldsm4(uint32_t& r0, uint32_t& r1,
                                      uint32_t& r2, uint32_t& r3, uint32_t addr) {
    asm volatile("ldmatrix.sync.aligned.m8n8.x4.shared.b16 {%0,%1,%2,%3}, [%4];"
                 : "=r"(r0), "=r"(r1), "=r"(r2), "=r"(r3) : "r"(addr));
}

// ---------------- prep: convert weights / activations to fp16 --------------
__global__ __launch_bounds__(256)
void cvt_weights(const float* __restrict__ Wq, const float* __restrict__ Wk,
                 const float* __restrict__ Wv, const float* __restrict__ Wo)
{
    int f = blockIdx.x * 256 + threadIdx.x;     // float4 index across 4 weights
    int w  = f / (WELTS / 4);
    int e4 = (f - w * (WELTS / 4)) * 4;
    const float* W = (w == 0) ? Wq : (w == 1) ? Wk : (w == 2) ? Wv : Wo;
    float4 a = *(const float4*)&W[e4];
    uint2 hp;
    hp.x = pack_h2(__float2half_rn(a.x), __float2half_rn(a.y));
    hp.y = pack_h2(__float2half_rn(a.z), __float2half_rn(a.w));
    *(uint2*)&g_wh[(size_t)w * WELTS + e4] = hp;
}

__global__ __launch_bounds__(256)
void cvt_x(const float* __restrict__ x)
{
    size_t f = (size_t)blockIdx.x * 256 + threadIdx.x;   // float4 index
    float4 a = ((const float4*)x)[f];
    uint2 hp;
    hp.x = pack_h2(__float2half_rn(a.x), __float2half_rn(a.y));
    hp.y = pack_h2(__float2half_rn(a.z), __float2half_rn(a.w));
    ((uint2*)g_xh)[f] = hp;
}

// ---------------- GEMM: fp16 single-pass, double-buffered ------------------
// out[seg][r, c] = (sum_k A[r,k] * W[seg][c,k] + bias[seg][c]) * scale[seg]
//                  (+ res[r,c] if res)  where seg = blockIdx.x / 3.
#define BM 128
#define BN 64
#define BK 32
#define PADW 20                    // uint32 (fp16-pair) row stride: 16 + 4 pad
#define SM_A 0
#define SM_B (BM * PADW)           // 2560
#define BUFW (BM * PADW + BN * PADW)   // 3840 uint32 per buffer
#define GEMM_SMEM (2 * BUFW * 4)       // 30720 bytes

struct GemmArgs {
    int          plane[3];  // plane index in g_wh
    const float* bias[3];
    float*       out[3];
    float        scale[3];
    const float* res;
};

__global__ __launch_bounds__(256)
void gemm_fp16(const __half* __restrict__ Abase, GemmArgs args)
{
    extern __shared__ uint32_t smem[];          // 2 * BUFW

    const int col0g = blockIdx.x * BN;
    const int seg   = col0g / DD;
    const int lc0   = col0g - seg * DD;
    const int row0  = blockIdx.y * BM;

    const uint4* __restrict__ A4 = (const uint4*)Abase;            // 24 uint4/row
    const uint4* __restrict__ W4 =
        (const uint4*)(g_wh + (size_t)args.plane[seg] * WELTS);

    const int tid  = threadIdx.x;
    const int lane = tid & 31;
    const int warp = tid >> 5;
    const int wm   = (warp & 3) * 32;   // 4 warps in m
    const int wn   = (warp >> 2) * 32;  // 2 warps in n
    const int g    = lane >> 2;
    const int t    = lane & 3;

    const uint32_t smem_base = (uint32_t)__cvta_generic_to_shared(smem);

    // per-lane ldmatrix geometry (word units; x4 tile order matches mma map)
    const int arow  = wm + (lane & 15);
    const int aksel = (lane >> 4) * 4;
    const int brow  = wn + (lane & 7) + ((lane >> 4) << 3);
    const int bksel = ((lane >> 3) & 1) * 4;

    float acc[2][4][4];
    #pragma unroll
    for (int i = 0; i < 2; i++)
        #pragma unroll
        for (int j = 0; j < 4; j++)
            #pragma unroll
            for (int c = 0; c < 4; c++) acc[i][j][c] = 0.f;

    // ---- staging helpers ---------------------------------------------------
    auto load_chunk = [&](int c, uint4* na, uint4* nb) {
        #pragma unroll
        for (int i = 0; i < 2; i++) {
            int idx = tid + i * 256;            // 0..511
            int m = idx >> 2, q4 = idx & 3;
            na[i] = A4[(size_t)(row0 + m) * 24 + c * 4 + q4];
        }
        {
            int n = tid >> 2, q4 = tid & 3;     // 256 uint4
            nb[0] = W4[(size_t)(lc0 + n) * 24 + c * 4 + q4];
        }
    };
    auto store_chunk = [&](uint32_t* buf, const uint4* na, const uint4* nb) {
        #pragma unroll
        for (int i = 0; i < 2; i++) {
            int idx = tid + i * 256;
            int m = idx >> 2, q4 = idx & 3;
            *(uint4*)&buf[SM_A + m * PADW + q4 * 4] = na[i];
        }
        {
            int n = tid >> 2, q4 = tid & 3;
            *(uint4*)&buf[SM_B + n * PADW + q4 * 4] = nb[0];
        }
    };

    // ---- prologue ----------------------------------------------------------
    {
        uint4 pa[2], pb[1];
        load_chunk(0, pa, pb);
        store_chunk(smem, pa, pb);
    }
    __syncthreads();

    // ---- pipelined main loop over 6 chunks ---------------------------------
    #pragma unroll
    for (int c = 0; c < 6; c++) {
        uint32_t* nxt = smem + ((c + 1) & 1) * BUFW;
        const uint32_t bufb = smem_base + (uint32_t)((c & 1) * BUFW) * 4;
        uint4 na[2], nb[1];
        if (c < 5) load_chunk(c + 1, na, nb);

        #pragma unroll
        for (int ks = 0; ks < 2; ks++) {
            const int kpb = ks * 8;
            uint32_t ah[2][4];
            #pragma unroll
            for (int mt = 0; mt < 2; mt++) {
                uint32_t aaddr = bufb +
                    (uint32_t)(SM_A + (arow + mt * 16) * PADW + kpb + aksel) * 4;
                ldsm4(ah[mt][0], ah[mt][1], ah[mt][2], ah[mt][3], aaddr);
            }
            uint32_t bh[4][2];
            #pragma unroll
            for (int p = 0; p < 2; p++) {
                uint32_t baddr = bufb +
                    (uint32_t)(SM_B + (brow + p * 16) * PADW + kpb + bksel) * 4;
                ldsm4(bh[2*p][0], bh[2*p][1], bh[2*p+1][0], bh[2*p+1][1], baddr);
            }
            #pragma unroll
            for (int mt = 0; mt < 2; mt++)
                #pragma unroll
                for (int nt = 0; nt < 4; nt++)
                    mma16(acc[mt][nt], ah[mt], bh[nt]);
        }

        if (c < 5) store_chunk(nxt, na, nb);
        __syncthreads();
    }

    // ---- epilogue ----------------------------------------------------------
    const float scale = args.scale[seg];
    float* const outp = args.out[seg];
    const float* const bias = args.bias[seg];
    const float* const res  = args.res;

    #pragma unroll
    for (int mt = 0; mt < 2; mt++) {
        #pragma unroll
        for (int nt = 0; nt < 4; nt++) {
            int row = row0 + wm + mt * 16 + g;
            int col = lc0 + wn + nt * 8 + t * 2;
            float b0 = bias[col], b1 = bias[col + 1];
            #pragma unroll
            for (int half = 0; half < 2; half++) {
                int r = row + half * 8;
                float v0 = (acc[mt][nt][half * 2 + 0] + b0) * scale;
                float v1 = (acc[mt][nt][half * 2 + 1] + b1) * scale;
                if (res != nullptr) {
                    const float2 rv = *(const float2*)&res[(size_t)r * DD + col];
                    v0 += rv.x; v1 += rv.y;
                }
                float2 o; o.x = v0; o.y = v1;
                *(float2*)&outp[(size_t)r * DD + col] = o;
            }
        }
    }
}

// ---------------- banded attention: window d in [-2, 2] --------------------
#define TS 16
#define KVROWS (TS + 4)

__global__ __launch_bounds__(256)
void band_attn(const float* __restrict__ mask0)
{
    __shared__ float ks[KVROWS * DD];
    __shared__ float vs[KVROWS * DD];
    __shared__ float msk[KVROWS];

    const int chunk = blockIdx.x;
    const int b  = chunk / (SEQ / TS);
    const int s0 = (chunk % (SEQ / TS)) * TS;
    const int tid = threadIdx.x;

    for (int i4 = tid; i4 < KVROWS * (DD / 4); i4 += 256) {
        int r  = i4 / (DD / 4);
        int c4 = i4 % (DD / 4);
        int s  = s0 - 2 + r;
        float4 kv = make_float4(0.f, 0.f, 0.f, 0.f);
        float4 vv = make_float4(0.f, 0.f, 0.f, 0.f);
        if (s >= 0 && s < SEQ) {
            size_t off = (size_t)(b * SEQ + s) * DD + c4 * 4;
            kv = *(const float4*)&g_k[off];
            vv = *(const float4*)&g_v[off];
        }
        *(float4*)&ks[r * DD + c4 * 4] = kv;
        *(float4*)&vs[r * DD + c4 * 4] = vv;
    }
    if (tid < KVROWS) {
        int s = s0 - 2 + tid;
        msk[tid] = (s >= 0 && s < SEQ) ? mask0[b * SEQ + s] : 0.f;
    }
    __syncthreads();

    const int sl = tid >> 4;
    const int h  = tid & 15;
    const int s  = s0 + sl;

    float q[HDIM];
    {
        const float* qp = &g_q[(size_t)(b * SEQ + s) * DD + h * HDIM];
        float4 q0 = *(const float4*)(qp + 0);
        float4 q1 = *(const float4*)(qp + 4);
        float4 q2 = *(const float4*)(qp + 8);
        q[0]=q0.x; q[1]=q0.y; q[2]=q0.z;  q[3]=q0.w;
        q[4]=q1.x; q[5]=q1.y; q[6]=q1.z;  q[7]=q1.w;
        q[8]=q2.x; q[9]=q2.y; q[10]=q2.z; q[11]=q2.w;
    }

    const float NEG  = -3.402823466e38f;
    const float NINF = __int_as_float(0xff800000);

    float sc[5];
    #pragma unroll
    for (int d = 0; d < 5; d++) {
        int r = sl + d;
        int skey = s + d - 2;
        const float* kp = &ks[r * DD + h * HDIM];
        float dot = 0.f;
        #pragma unroll
        for (int j = 0; j < HDIM; j++) dot += q[j] * kp[j];
        float fm = (msk[r] != 0.f) ? NEG : 0.f;
        sc[d] = (skey >= 0 && skey < SEQ) ? (dot + fm) : NINF;
    }

    float mx = sc[0];
    #pragma unroll
    for (int d = 1; d < 5; d++) mx = fmaxf(mx, sc[d]);
    float e[5], sum = 0.f;
    #pragma unroll
    for (int d = 0; d < 5; d++) { e[d] = expf(sc[d] - mx); sum += e[d]; }
    float inv = 1.f / sum;
    bool index_masked = (msk[sl + 2] < 0.f);

    float c[HDIM] = {};
    #pragma unroll
    for (int d = 0; d < 5; d++) {
        float p = index_masked ? 0.f : e[d] * inv;
        const float* vp = &vs[(sl + d) * DD + h * HDIM];
        #pragma unroll
        for (int j = 0; j < HDIM; j++) c[j] += p * vp[j];
    }

    // write ctx directly as fp16 (12 halves = 6 packed uint32)
    size_t base = (size_t)(b * SEQ + s) * DD + h * HDIM;
    uint32_t* oc = (uint32_t*)(g_ctxh + base);
    #pragma unroll
    for (int j = 0; j < 6; j++)
        oc[j] = pack_h2(__float2half_rn(c[2*j]), __float2half_rn(c[2*j+1]));
}

// ---------------- LayerNorm over the last dim (192), warp per row ----------
__global__ __launch_bounds__(256)
void layernorm(const float* __restrict__ ln_g, const float* __restrict__ ln_b,
               float* __restrict__ out)
{
    const int row  = blockIdx.x * 8 + (threadIdx.x >> 5);
    const int lane = threadIdx.x & 31;

    const float* hp = &g_q[(size_t)row * DD];  // g_q holds h after O-proj
    float h[6];
    float sum = 0.f;
    #pragma unroll
    for (int j = 0; j < 6; j++) { h[j] = hp[lane + j * 32]; sum += h[j]; }
    #pragma unroll
    for (int o = 16; o > 0; o >>= 1) sum += __shfl_xor_sync(0xffffffffu, sum, o);
    float mu = sum * (1.f / 192.f);

    float s2 = 0.f;
    #pragma unroll
    for (int j = 0; j < 6; j++) { float d = h[j] - mu; s2 += d * d; }
    #pragma unroll
    for (int o = 16; o > 0; o >>= 1) s2 += __shfl_xor_sync(0xffffffffu, s2, o);
    float invstd = rsqrtf(s2 * (1.f / 192.f) + 1e-12f);

    float* op = &out[(size_t)row * DD];
    #pragma unroll
    for (int j = 0; j < 6; j++) {
        int cc = lane + j * 32;
        op[cc] = (h[j] - mu) * invstd * ln_g[cc] + ln_b[cc];
    }
}

// ---------------- launch ---------------------------------------------------
extern "C" void kernel_launch(void* const* d_in, const int* in_sizes, int n_in,
                              void* d_out, int out_size)
{
    const float* x     = (const float*)d_in[0];
    const float* mask0 = (const float*)d_in[1];
    const float* bq    = (const float*)d_in[3];
    const float* bk    = (const float*)d_in[5];
    const float* bv    = (const float*)d_in[7];
    const float* bo    = (const float*)d_in[9];
    const float* ln_g  = (const float*)d_in[10];
    const float* ln_b  = (const float*)d_in[11];
    float* out = (float*)d_out;

    float *pq, *pk, *pv;
    __half *pxh, *pch;
    cudaGetSymbolAddress((void**)&pq,  g_q);
    cudaGetSymbolAddress((void**)&pk,  g_k);
    cudaGetSymbolAddress((void**)&pv,  g_v);
    cudaGetSymbolAddress((void**)&pxh, g_xh);
    cudaGetSymbolAddress((void**)&pch, g_ctxh);

    cudaFuncSetAttribute(gemm_fp16, cudaFuncAttributeMaxDynamicSharedMemorySize,
                         GEMM_SMEM);

    const float qscale = 0.28867513459481287f;  // 1/sqrt(12)

    cvt_weights<<<4 * WELTS / 4 / 256, 256>>>((const float*)d_in[2],
                                              (const float*)d_in[4],
                                              (const float*)d_in[6],
                                              (const float*)d_in[8]);
    cvt_x<<<NROWS * DD / 4 / 256, 256>>>(x);

    // Fused QKV: 9 n-blocks (3 segs x 3 cols), n fast for L2 reuse of A rows
    GemmArgs qkv;
    qkv.plane[0] = 0; qkv.plane[1] = 1; qkv.plane[2] = 2;
    qkv.bias[0] = bq; qkv.bias[1] = bk; qkv.bias[2] = bv;
    qkv.out[0] = pq;  qkv.out[1] = pk;  qkv.out[2] = pv;
    qkv.scale[0] = qscale; qkv.scale[1] = 1.f; qkv.scale[2] = 1.f;
    qkv.res = nullptr;
    dim3 qkv_grid(3 * DD / BN, NROWS / BM);     // (9, 1024)
    gemm_fp16<<<qkv_grid, 256, GEMM_SMEM>>>(pxh, qkv);

    band_attn<<<BATCH * (SEQ / TS), 256>>>(mask0);

    // Output projection + residual -> g_q (becomes h)
    GemmArgs og;
    og.plane[0] = 3; og.plane[1] = 3; og.plane[2] = 3;
    og.bias[0] = bo; og.bias[1] = bo; og.bias[2] = bo;
    og.out[0] = pq; og.out[1] = pq; og.out[2] = pq;
    og.scale[0] = 1.f; og.scale[1] = 1.f; og.scale[2] = 1.f;
    og.res = x;
    dim3 o_grid(DD / BN, NROWS / BM);           // (3, 1024)
    gemm_fp16<<<o_grid, 256, GEMM_SMEM>>>(pch, og);

    layernorm<<<NROWS / 8, 256>>>(ln_g, ln_b, out);
}

// round 15
// speedup vs baseline: 2.3283x; 1.0110x over previous
#include <cuda_runtime.h>
#include <cuda_fp16.h>
#include <math.h>
#include <stdint.h>

// Problem dims (fixed by the dataset)
#define DD    192
#define HDIM  12
#define SEQ   8192
#define BATCH 16
#define NROWS (BATCH * SEQ)
#define WELTS (DD * DD)         // 36864 elements per weight

// ---------------- scratch (static device globals) -------------------------
__device__ float g_q[(size_t)NROWS * DD];
__device__ float g_k[(size_t)NROWS * DD];
__device__ float g_v[(size_t)NROWS * DD];
__device__ __half g_xh[(size_t)NROWS * DD];     // x as fp16
__device__ __half g_ctxh[(size_t)NROWS * DD];   // attention context as fp16
__device__ __half g_wh[(size_t)4 * WELTS];      // Wq,Wk,Wv,Wo as fp16

// ---------------- helpers --------------------------------------------------
__device__ __forceinline__ uint32_t pack_h2(__half a, __half b) {
    return (uint32_t)__half_as_ushort(a) | ((uint32_t)__half_as_ushort(b) << 16);
}

// fp16 m16n8k16 mma, fp32 accumulate
__device__ __forceinline__ void mma16(float* c, const uint32_t* a, const uint32_t* b) {
    asm volatile(
        "mma.sync.aligned.m16n8k16.row.col.f32.f16.f16.f32 "
        "{%0,%1,%2,%3}, {%4,%5,%6,%7}, {%8,%9}, {%0,%1,%2,%3};"
        : "+f"(c[0]), "+f"(c[1]), "+f"(c[2]), "+f"(c[3])
        : "r"(a[0]), "r"(a[1]), "r"(a[2]), "r"(a[3]), "r"(b[0]), "r"(b[1]));
}

// ldmatrix: 4x 8x8 b16 tiles, per-lane addresses
__device__ __forceinline__ void ldsm4(uint32_t& r0, uint32_t& r1,
                                      uint32_t& r2, uint32_t& r3, uint32_t addr) {
    asm volatile("ldmatrix.sync.aligned.m8n8.x4.shared.b16 {%0,%1,%2,%3}, [%4];"
                 : "=r"(r0), "=r"(r1), "=r"(r2), "=r"(r3) : "r"(addr));
}

// ---------------- prep: convert weights / activations to fp16 --------------
__global__ __launch_bounds__(256)
void cvt_weights(const float* __restrict__ Wq, const float* __restrict__ Wk,
                 const float* __restrict__ Wv, const float* __restrict__ Wo)
{
    int f = blockIdx.x * 256 + threadIdx.x;     // float4 index across 4 weights
    int w  = f / (WELTS / 4);
    int e4 = (f - w * (WELTS / 4)) * 4;
    const float* W = (w == 0) ? Wq : (w == 1) ? Wk : (w == 2) ? Wv : Wo;
    float4 a = *(const float4*)&W[e4];
    uint2 hp;
    hp.x = pack_h2(__float2half_rn(a.x), __float2half_rn(a.y));
    hp.y = pack_h2(__float2half_rn(a.z), __float2half_rn(a.w));
    *(uint2*)&g_wh[(size_t)w * WELTS + e4] = hp;
}

__global__ __launch_bounds__(256)
void cvt_x(const float* __restrict__ x)
{
    size_t f = (size_t)blockIdx.x * 256 + threadIdx.x;   // float4 index
    float4 a = ((const float4*)x)[f];
    uint2 hp;
    hp.x = pack_h2(__float2half_rn(a.x), __float2half_rn(a.y));
    hp.y = pack_h2(__float2half_rn(a.z), __float2half_rn(a.w));
    ((uint2*)g_xh)[f] = hp;
}

// ---------------- GEMM: fp16, full-K-resident tiles (no pipeline) ----------
// out[seg][r, c] = (sum_k A[r,k] * W[seg][c,k] + bias[seg][c]) * scale[seg]
//                  (+ res[r,c] if res)  where seg = blockIdx.x / 3.
#define BM 128
#define BN 64
#define PADA 100                   // uint32 (fp16-pair) row stride: 96 + 4 pad
#define SM_A 0
#define SM_B (BM * PADA)           // 12800 words
#define GEMM_SMEM ((BM * PADA + BN * PADA) * 4)   // 76800 bytes

struct GemmArgs {
    int          plane[3];  // plane index in g_wh
    const float* bias[3];
    float*       out[3];
    float        scale[3];
    const float* res;
};

__global__ __launch_bounds__(256)
void gemm_fp16(const __half* __restrict__ Abase, GemmArgs args)
{
    extern __shared__ uint32_t smem[];

    const int col0g = blockIdx.x * BN;
    const int seg   = col0g / DD;
    const int lc0   = col0g - seg * DD;
    const int row0  = blockIdx.y * BM;

    const uint4* __restrict__ A4 = (const uint4*)Abase;            // 24 uint4/row
    const uint4* __restrict__ W4 =
        (const uint4*)(g_wh + (size_t)args.plane[seg] * WELTS);

    const int tid  = threadIdx.x;
    const int lane = tid & 31;
    const int warp = tid >> 5;
    const int wm   = (warp & 3) * 32;   // 4 warps in m
    const int wn   = (warp >> 2) * 32;  // 2 warps in n
    const int g    = lane >> 2;
    const int t    = lane & 3;

    const uint32_t smem_base = (uint32_t)__cvta_generic_to_shared(smem);

    // per-lane ldmatrix geometry (word units; x4 tile order matches mma map)
    const int arow  = wm + (lane & 15);
    const int aksel = (lane >> 4) * 4;
    const int brow  = wn + (lane & 7) + ((lane >> 4) << 3);
    const int bksel = ((lane >> 3) & 1) * 4;

    float acc[2][4][4];
    #pragma unroll
    for (int i = 0; i < 2; i++)
        #pragma unroll
        for (int j = 0; j < 4; j++)
            #pragma unroll
            for (int c = 0; c < 4; c++) acc[i][j][c] = 0.f;

    // ---- stage the FULL K=192 tile once: 18 independent LDG.128/thread ----
    #pragma unroll
    for (int i = 0; i < 12; i++) {               // A: 3072 uint4
        int idx = tid + i * 256;
        int m = idx / 24, q = idx - m * 24;
        *(uint4*)&smem[SM_A + m * PADA + q * 4] =
            A4[(size_t)(row0 + m) * 24 + q];
    }
    #pragma unroll
    for (int i = 0; i < 6; i++) {                // B: 1536 uint4
        int idx = tid + i * 256;
        int n = idx / 24, q = idx - n * 24;
        *(uint4*)&smem[SM_B + n * PADA + q * 4] =
            W4[(size_t)(lc0 + n) * 24 + q];
    }
    __syncthreads();

    // ---- 12 uninterrupted ks-steps of pure LDSM + MMA ----------------------
    #pragma unroll
    for (int ks = 0; ks < 12; ks++) {
        const int kpb = ks * 8;
        uint32_t ah[2][4];
        #pragma unroll
        for (int mt = 0; mt < 2; mt++) {
            uint32_t aaddr = smem_base +
                (uint32_t)(SM_A + (arow + mt * 16) * PADA + kpb + aksel) * 4;
            ldsm4(ah[mt][0], ah[mt][1], ah[mt][2], ah[mt][3], aaddr);
        }
        uint32_t bh[4][2];
        #pragma unroll
        for (int p = 0; p < 2; p++) {
            uint32_t baddr = smem_base +
                (uint32_t)(SM_B + (brow + p * 16) * PADA + kpb + bksel) * 4;
            ldsm4(bh[2*p][0], bh[2*p][1], bh[2*p+1][0], bh[2*p+1][1], baddr);
        }
        #pragma unroll
        for (int mt = 0; mt < 2; mt++)
            #pragma unroll
            for (int nt = 0; nt < 4; nt++)
                mma16(acc[mt][nt], ah[mt], bh[nt]);
    }

    // ---- epilogue ----------------------------------------------------------
    const float scale = args.scale[seg];
    float* const outp = args.out[seg];
    const float* const bias = args.bias[seg];
    const float* const res  = args.res;

    #pragma unroll
    for (int mt = 0; mt < 2; mt++) {
        #pragma unroll
        for (int nt = 0; nt < 4; nt++) {
            int row = row0 + wm + mt * 16 + g;
            int col = lc0 + wn + nt * 8 + t * 2;
            float b0 = bias[col], b1 = bias[col + 1];
            #pragma unroll
            for (int half = 0; half < 2; half++) {
                int r = row + half * 8;
                float v0 = (acc[mt][nt][half * 2 + 0] + b0) * scale;
                float v1 = (acc[mt][nt][half * 2 + 1] + b1) * scale;
                if (res != nullptr) {
                    const float2 rv = *(const float2*)&res[(size_t)r * DD + col];
                    v0 += rv.x; v1 += rv.y;
                }
                float2 o; o.x = v0; o.y = v1;
                *(float2*)&outp[(size_t)r * DD + col] = o;
            }
        }
    }
}

// ---------------- banded attention: window d in [-2, 2] --------------------
#define TS 16
#define KVROWS (TS + 4)

__global__ __launch_bounds__(256)
void band_attn(const float* __restrict__ mask0)
{
    __shared__ float ks[KVROWS * DD];
    __shared__ float vs[KVROWS * DD];
    __shared__ float msk[KVROWS];

    const int chunk = blockIdx.x;
    const int b  = chunk / (SEQ / TS);
    const int s0 = (chunk % (SEQ / TS)) * TS;
    const int tid = threadIdx.x;

    for (int i4 = tid; i4 < KVROWS * (DD / 4); i4 += 256) {
        int r  = i4 / (DD / 4);
        int c4 = i4 % (DD / 4);
        int s  = s0 - 2 + r;
        float4 kv = make_float4(0.f, 0.f, 0.f, 0.f);
        float4 vv = make_float4(0.f, 0.f, 0.f, 0.f);
        if (s >= 0 && s < SEQ) {
            size_t off = (size_t)(b * SEQ + s) * DD + c4 * 4;
            kv = *(const float4*)&g_k[off];
            vv = *(const float4*)&g_v[off];
        }
        *(float4*)&ks[r * DD + c4 * 4] = kv;
        *(float4*)&vs[r * DD + c4 * 4] = vv;
    }
    if (tid < KVROWS) {
        int s = s0 - 2 + tid;
        msk[tid] = (s >= 0 && s < SEQ) ? mask0[b * SEQ + s] : 0.f;
    }
    __syncthreads();

    const int sl = tid >> 4;
    const int h  = tid & 15;
    const int s  = s0 + sl;

    float q[HDIM];
    {
        const float* qp = &g_q[(size_t)(b * SEQ + s) * DD + h * HDIM];
        float4 q0 = *(const float4*)(qp + 0);
        float4 q1 = *(const float4*)(qp + 4);
        float4 q2 = *(const float4*)(qp + 8);
        q[0]=q0.x; q[1]=q0.y; q[2]=q0.z;  q[3]=q0.w;
        q[4]=q1.x; q[5]=q1.y; q[6]=q1.z;  q[7]=q1.w;
        q[8]=q2.x; q[9]=q2.y; q[10]=q2.z; q[11]=q2.w;
    }

    const float NEG  = -3.402823466e38f;
    const float NINF = __int_as_float(0xff800000);

    float sc[5];
    #pragma unroll
    for (int d = 0; d < 5; d++) {
        int r = sl + d;
        int skey = s + d - 2;
        const float* kp = &ks[r * DD + h * HDIM];
        float dot = 0.f;
        #pragma unroll
        for (int j = 0; j < HDIM; j++) dot += q[j] * kp[j];
        float fm = (msk[r] != 0.f) ? NEG : 0.f;
        sc[d] = (skey >= 0 && skey < SEQ) ? (dot + fm) : NINF;
    }

    float mx = sc[0];
    #pragma unroll
    for (int d = 1; d < 5; d++) mx = fmaxf(mx, sc[d]);
    float e[5], sum = 0.f;
    #pragma unroll
    for (int d = 0; d < 5; d++) { e[d] = expf(sc[d] - mx); sum += e[d]; }
    float inv = 1.f / sum;
    bool index_masked = (msk[sl + 2] < 0.f);

    float c[HDIM] = {};
    #pragma unroll
    for (int d = 0; d < 5; d++) {
        float p = index_masked ? 0.f : e[d] * inv;
        const float* vp = &vs[(sl + d) * DD + h * HDIM];
        #pragma unroll
        for (int j = 0; j < HDIM; j++) c[j] += p * vp[j];
    }

    // write ctx directly as fp16 (12 halves = 6 packed uint32)
    size_t base = (size_t)(b * SEQ + s) * DD + h * HDIM;
    uint32_t* oc = (uint32_t*)(g_ctxh + base);
    #pragma unroll
    for (int j = 0; j < 6; j++)
        oc[j] = pack_h2(__float2half_rn(c[2*j]), __float2half_rn(c[2*j+1]));
}

// ---------------- LayerNorm over the last dim (192), warp per row ----------
__global__ __launch_bounds__(256)
void layernorm(const float* __restrict__ ln_g, const float* __restrict__ ln_b,
               float* __restrict__ out)
{
    const int row  = blockIdx.x * 8 + (threadIdx.x >> 5);
    const int lane = threadIdx.x & 31;

    const float* hp = &g_q[(size_t)row * DD];  // g_q holds h after O-proj
    float h[6];
    float sum = 0.f;
    #pragma unroll
    for (int j = 0; j < 6; j++) { h[j] = hp[lane + j * 32]; sum += h[j]; }
    #pragma unroll
    for (int o = 16; o > 0; o >>= 1) sum += __shfl_xor_sync(0xffffffffu, sum, o);
    float mu = sum * (1.f / 192.f);

    float s2 = 0.f;
    #pragma unroll
    for (int j = 0; j < 6; j++) { float d = h[j] - mu; s2 += d * d; }
    #pragma unroll
    for (int o = 16; o > 0; o >>= 1) s2 += __shfl_xor_sync(0xffffffffu, s2, o);
    float invstd = rsqrtf(s2 * (1.f / 192.f) + 1e-12f);

    float* op = &out[(size_t)row * DD];
    #pragma unroll
    for (int j = 0; j < 6; j++) {
        int cc = lane + j * 32;
        op[cc] = (h[j] - mu) * invstd * ln_g[cc] + ln_b[cc];
    }
}

// ---------------- launch ---------------------------------------------------
extern "C" void kernel_launch(void* const* d_in, const int* in_sizes, int n_in,
                              void* d_out, int out_size)
{
    const float* x     = (const float*)d_in[0];
    const float* mask0 = (const float*)d_in[1];
    const float* bq    = (const float*)d_in[3];
    const float* bk    = (const float*)d_in[5];
    const float* bv    = (const float*)d_in[7];
    const float* bo    = (const float*)d_in[9];
    const float* ln_g  = (const float*)d_in[10];
    const float* ln_b  = (const float*)d_in[11];
    float* out = (float*)d_out;

    float *pq, *pk, *pv;
    __half *pxh, *pch;
    cudaGetSymbolAddress((void**)&pq,  g_q);
    cudaGetSymbolAddress((void**)&pk,  g_k);
    cudaGetSymbolAddress((void**)&pv,  g_v);
    cudaGetSymbolAddress((void**)&pxh, g_xh);
    cudaGetSymbolAddress((void**)&pch, g_ctxh);

    cudaFuncSetAttribute(gemm_fp16, cudaFuncAttributeMaxDynamicSharedMemorySize,
                         GEMM_SMEM);

    const float qscale = 0.28867513459481287f;  // 1/sqrt(12)

    cvt_weights<<<4 * WELTS / 4 / 256, 256>>>((const float*)d_in[2],
                                              (const float*)d_in[4],
                                              (const float*)d_in[6],
                                              (const float*)d_in[8]);
    cvt_x<<<NROWS * DD / 4 / 256, 256>>>(x);

    // Fused QKV: 9 n-blocks (3 segs x 3 cols), n fast for L2 reuse of A rows
    GemmArgs qkv;
    qkv.plane[0] = 0; qkv.plane[1] = 1; qkv.plane[2] = 2;
    qkv.bias[0] = bq; qkv.bias[1] = bk; qkv.bias[2] = bv;
    qkv.out[0] = pq;  qkv.out[1] = pk;  qkv.out[2] = pv;
    qkv.scale[0] = qscale; qkv.scale[1] = 1.f; qkv.scale[2] = 1.f;
    qkv.res = nullptr;
    dim3 qkv_grid(3 * DD / BN, NROWS / BM);     // (9, 1024)
    gemm_fp16<<<qkv_grid, 256, GEMM_SMEM>>>(pxh, qkv);

    band_attn<<<BATCH * (SEQ / TS), 256>>>(mask0);

    // Output projection + residual -> g_q (becomes h)
    GemmArgs og;
    og.plane[0] = 3; og.plane[1] = 3; og.plane[2] = 3;
    og.bias[0] = bo; og.bias[1] = bo; og.bias[2] = bo;
    og.out[0] = pq; og.out[1] = pq; og.out[2] = pq;
    og.scale[0] = 1.f; og.scale[1] = 1.f; og.scale[2] = 1.f;
    og.res = x;
    dim3 o_grid(DD / BN, NROWS / BM);           // (3, 1024)
    gemm_fp16<<<o_grid, 256, GEMM_SMEM>>>(pch, og);

    layernorm<<<NROWS / 8, 256>>>(ln_g, ln_b, out);
}

// round 16
// speedup vs baseline: 2.4708x; 1.0612x over previous
#include <cuda_runtime.h>
#include <cuda_fp16.h>
#include <math.h>
#include <stdint.h>

// Problem dims (fixed by the dataset)
#define DD    192
#define HDIM  12
#define SEQ   8192
#define BATCH 16
#define NROWS (BATCH * SEQ)
#define WELTS (DD * DD)         // 36864 elements per weight

// ---------------- scratch (static device globals) -------------------------
__device__ __half g_qh[(size_t)NROWS * DD];     // q (pre-scaled) fp16
__device__ __half g_kh[(size_t)NROWS * DD];     // k fp16
__device__ __half g_vh[(size_t)NROWS * DD];     // v fp16
__device__ __half g_xh[(size_t)NROWS * DD];     // x as fp16
__device__ __half g_ctxh[(size_t)NROWS * DD];   // attention context fp16
__device__ float  g_hf[(size_t)NROWS * DD];     // pre-LN h (fp32)
__device__ __half g_wh[(size_t)4 * WELTS];      // Wq,Wk,Wv,Wo as fp16

// ---------------- helpers --------------------------------------------------
__device__ __forceinline__ uint32_t pack_h2(__half a, __half b) {
    return (uint32_t)__half_as_ushort(a) | ((uint32_t)__half_as_ushort(b) << 16);
}

// fp16 m16n8k16 mma, fp32 accumulate
__device__ __forceinline__ void mma16(float* c, const uint32_t* a, const uint32_t* b) {
    asm volatile(
        "mma.sync.aligned.m16n8k16.row.col.f32.f16.f16.f32 "
        "{%0,%1,%2,%3}, {%4,%5,%6,%7}, {%8,%9}, {%0,%1,%2,%3};"
        : "+f"(c[0]), "+f"(c[1]), "+f"(c[2]), "+f"(c[3])
        : "r"(a[0]), "r"(a[1]), "r"(a[2]), "r"(a[3]), "r"(b[0]), "r"(b[1]));
}

// ldmatrix: 4x 8x8 b16 tiles, per-lane addresses
__device__ __forceinline__ void ldsm4(uint32_t& r0, uint32_t& r1,
                                      uint32_t& r2, uint32_t& r3, uint32_t addr) {
    asm volatile("ldmatrix.sync.aligned.m8n8.x4.shared.b16 {%0,%1,%2,%3}, [%4];"
                 : "=r"(r0), "=r"(r1), "=r"(r2), "=r"(r3) : "r"(addr));
}

// ---------------- prep: convert weights / activations to fp16 --------------
__global__ __launch_bounds__(256)
void cvt_weights(const float* __restrict__ Wq, const float* __restrict__ Wk,
                 const float* __restrict__ Wv, const float* __restrict__ Wo)
{
    int f = blockIdx.x * 256 + threadIdx.x;     // float4 index across 4 weights
    int w  = f / (WELTS / 4);
    int e4 = (f - w * (WELTS / 4)) * 4;
    const float* W = (w == 0) ? Wq : (w == 1) ? Wk : (w == 2) ? Wv : Wo;
    float4 a = *(const float4*)&W[e4];
    uint2 hp;
    hp.x = pack_h2(__float2half_rn(a.x), __float2half_rn(a.y));
    hp.y = pack_h2(__float2half_rn(a.z), __float2half_rn(a.w));
    *(uint2*)&g_wh[(size_t)w * WELTS + e4] = hp;
}

__global__ __launch_bounds__(256)
void cvt_x(const float* __restrict__ x)
{
    size_t f = (size_t)blockIdx.x * 256 + threadIdx.x;   // float4 index
    float4 a = ((const float4*)x)[f];
    uint2 hp;
    hp.x = pack_h2(__float2half_rn(a.x), __float2half_rn(a.y));
    hp.y = pack_h2(__float2half_rn(a.z), __float2half_rn(a.w));
    ((uint2*)g_xh)[f] = hp;
}

// ---------------- GEMM: fp16, full-K-resident tiles -------------------------
// out[seg][r, c] = (sum_k A[r,k] * W[seg][c,k] + bias[seg][c]) * scale[seg]
//                  (+ res[r,c] if res);  fp16 or fp32 output per out_half.
#define BM 128
#define BN 64
#define PADA 100                   // uint32 (fp16-pair) row stride: 96 + 4 pad
#define SM_A 0
#define SM_B (BM * PADA)           // 12800 words
#define GEMM_SMEM ((BM * PADA + BN * PADA) * 4)   // 76800 bytes

struct GemmArgs {
    int          plane[3];  // plane index in g_wh
    const float* bias[3];
    void*        out[3];
    float        scale[3];
    const float* res;
    int          out_half;  // 1: fp16 packed output, 0: fp32
};

__global__ __launch_bounds__(256)
void gemm_fp16(const __half* __restrict__ Abase, GemmArgs args)
{
    extern __shared__ uint32_t smem[];

    const int col0g = blockIdx.x * BN;
    const int seg   = col0g / DD;
    const int lc0   = col0g - seg * DD;
    const int row0  = blockIdx.y * BM;

    const uint4* __restrict__ A4 = (const uint4*)Abase;            // 24 uint4/row
    const uint4* __restrict__ W4 =
        (const uint4*)(g_wh + (size_t)args.plane[seg] * WELTS);

    const int tid  = threadIdx.x;
    const int lane = tid & 31;
    const int warp = tid >> 5;
    const int wm   = (warp & 3) * 32;   // 4 warps in m
    const int wn   = (warp >> 2) * 32;  // 2 warps in n
    const int g    = lane >> 2;
    const int t    = lane & 3;

    const uint32_t smem_base = (uint32_t)__cvta_generic_to_shared(smem);

    const int arow  = wm + (lane & 15);
    const int aksel = (lane >> 4) * 4;
    const int brow  = wn + (lane & 7) + ((lane >> 4) << 3);
    const int bksel = ((lane >> 3) & 1) * 4;

    float acc[2][4][4];
    #pragma unroll
    for (int i = 0; i < 2; i++)
        #pragma unroll
        for (int j = 0; j < 4; j++)
            #pragma unroll
            for (int c = 0; c < 4; c++) acc[i][j][c] = 0.f;

    // ---- stage the FULL K=192 tile once ------------------------------------
    #pragma unroll
    for (int i = 0; i < 12; i++) {               // A: 3072 uint4
        int idx = tid + i * 256;
        int m = idx / 24, q = idx - m * 24;
        *(uint4*)&smem[SM_A + m * PADA + q * 4] =
            A4[(size_t)(row0 + m) * 24 + q];
    }
    #pragma unroll
    for (int i = 0; i < 6; i++) {                // B: 1536 uint4
        int idx = tid + i * 256;
        int n = idx / 24, q = idx - n * 24;
        *(uint4*)&smem[SM_B + n * PADA + q * 4] =
            W4[(size_t)(lc0 + n) * 24 + q];
    }
    __syncthreads();

    // ---- 12 uninterrupted ks-steps of pure LDSM + MMA ----------------------
    #pragma unroll
    for (int ks = 0; ks < 12; ks++) {
        const int kpb = ks * 8;
        uint32_t ah[2][4];
        #pragma unroll
        for (int mt = 0; mt < 2; mt++) {
            uint32_t aaddr = smem_base +
                (uint32_t)(SM_A + (arow + mt * 16) * PADA + kpb + aksel) * 4;
            ldsm4(ah[mt][0], ah[mt][1], ah[mt][2], ah[mt][3], aaddr);
        }
        uint32_t bh[4][2];
        #pragma unroll
        for (int p = 0; p < 2; p++) {
            uint32_t baddr = smem_base +
                (uint32_t)(SM_B + (brow + p * 16) * PADA + kpb + bksel) * 4;
            ldsm4(bh[2*p][0], bh[2*p][1], bh[2*p+1][0], bh[2*p+1][1], baddr);
        }
        #pragma unroll
        for (int mt = 0; mt < 2; mt++)
            #pragma unroll
            for (int nt = 0; nt < 4; nt++)
                mma16(acc[mt][nt], ah[mt], bh[nt]);
    }

    // ---- epilogue ----------------------------------------------------------
    const float scale = args.scale[seg];
    const float* const bias = args.bias[seg];
    const float* const res  = args.res;

    #pragma unroll
    for (int mt = 0; mt < 2; mt++) {
        #pragma unroll
        for (int nt = 0; nt < 4; nt++) {
            int row = row0 + wm + mt * 16 + g;
            int col = lc0 + wn + nt * 8 + t * 2;
            float b0 = bias[col], b1 = bias[col + 1];
            #pragma unroll
            for (int half = 0; half < 2; half++) {
                int r = row + half * 8;
                float v0 = (acc[mt][nt][half * 2 + 0] + b0) * scale;
                float v1 = (acc[mt][nt][half * 2 + 1] + b1) * scale;
                if (res != nullptr) {
                    const float2 rv = *(const float2*)&res[(size_t)r * DD + col];
                    v0 += rv.x; v1 += rv.y;
                }
                if (args.out_half) {
                    __half* outp = (__half*)args.out[seg];
                    *(uint32_t*)&outp[(size_t)r * DD + col] =
                        pack_h2(__float2half_rn(v0), __float2half_rn(v1));
                } else {
                    float* outp = (float*)args.out[seg];
                    float2 o; o.x = v0; o.y = v1;
                    *(float2*)&outp[(size_t)r * DD + col] = o;
                }
            }
        }
    }
}

// ---------------- banded attention: window d in [-2, 2], fp16 I/O ----------
#define TS 16
#define KVROWS (TS + 4)

__global__ __launch_bounds__(256)
void band_attn(const float* __restrict__ mask0)
{
    __shared__ __half ks[KVROWS * DD];   // 7680 B
    __shared__ __half vs[KVROWS * DD];
    __shared__ float  msk[KVROWS];

    const int chunk = blockIdx.x;
    const int b  = chunk / (SEQ / TS);
    const int s0 = (chunk % (SEQ / TS)) * TS;
    const int tid = threadIdx.x;

    // Stage k, v rows [s0-2, s0+TS+2): 480 uint4 each (24 uint4 per row)
    for (int i4 = tid; i4 < KVROWS * 24; i4 += 256) {
        int r = i4 / 24;
        int c = i4 % 24;
        int s = s0 - 2 + r;
        uint4 kv = make_uint4(0, 0, 0, 0), vv = make_uint4(0, 0, 0, 0);
        if (s >= 0 && s < SEQ) {
            size_t off = (size_t)(b * SEQ + s) * DD + c * 8;
            kv = *(const uint4*)&g_kh[off];
            vv = *(const uint4*)&g_vh[off];
        }
        *(uint4*)&ks[r * DD + c * 8] = kv;
        *(uint4*)&vs[r * DD + c * 8] = vv;
    }
    if (tid < KVROWS) {
        int s = s0 - 2 + tid;
        msk[tid] = (s >= 0 && s < SEQ) ? mask0[b * SEQ + s] : 0.f;
    }
    __syncthreads();

    const int sl = tid >> 4;
    const int h  = tid & 15;
    const int s  = s0 + sl;

    // load q (fp16, pre-scaled) -> fp32
    float q[HDIM];
    {
        const __half2* qp = (const __half2*)&g_qh[(size_t)(b * SEQ + s) * DD + h * HDIM];
        #pragma unroll
        for (int j = 0; j < 6; j++) {
            float2 f = __half22float2(qp[j]);
            q[2*j] = f.x; q[2*j+1] = f.y;
        }
    }

    const float NEG  = -3.402823466e38f;
    const float NINF = __int_as_float(0xff800000);

    float sc[5];
    #pragma unroll
    for (int d = 0; d < 5; d++) {
        int r = sl + d;
        int skey = s + d - 2;
        const __half2* kp = (const __half2*)&ks[r * DD + h * HDIM];
        float dot = 0.f;
        #pragma unroll
        for (int j = 0; j < 6; j++) {
            float2 kf = __half22float2(kp[j]);
            dot += q[2*j] * kf.x + q[2*j+1] * kf.y;
        }
        float fm = (msk[r] != 0.f) ? NEG : 0.f;
        sc[d] = (skey >= 0 && skey < SEQ) ? (dot + fm) : NINF;
    }

    float mx = sc[0];
    #pragma unroll
    for (int d = 1; d < 5; d++) mx = fmaxf(mx, sc[d]);
    float e[5], sum = 0.f;
    #pragma unroll
    for (int d = 0; d < 5; d++) { e[d] = expf(sc[d] - mx); sum += e[d]; }
    float inv = 1.f / sum;
    bool index_masked = (msk[sl + 2] < 0.f);

    float c[HDIM] = {};
    #pragma unroll
    for (int d = 0; d < 5; d++) {
        float p = index_masked ? 0.f : e[d] * inv;
        const __half2* vp = (const __half2*)&vs[(sl + d) * DD + h * HDIM];
        #pragma unroll
        for (int j = 0; j < 6; j++) {
            float2 vf = __half22float2(vp[j]);
            c[2*j]   += p * vf.x;
            c[2*j+1] += p * vf.y;
        }
    }

    // write ctx as fp16 (12 halves = 6 packed uint32)
    size_t base = (size_t)(b * SEQ + s) * DD + h * HDIM;
    uint32_t* oc = (uint32_t*)(g_ctxh + base);
    #pragma unroll
    for (int j = 0; j < 6; j++)
        oc[j] = pack_h2(__float2half_rn(c[2*j]), __float2half_rn(c[2*j+1]));
}

// ---------------- LayerNorm over the last dim (192), warp per row ----------
__global__ __launch_bounds__(256)
void layernorm(const float* __restrict__ ln_g, const float* __restrict__ ln_b,
               float* __restrict__ out)
{
    const int row  = blockIdx.x * 8 + (threadIdx.x >> 5);
    const int lane = threadIdx.x & 31;

    const float* hp = &g_hf[(size_t)row * DD];
    float h[6];
    float sum = 0.f;
    #pragma unroll
    for (int j = 0; j < 6; j++) { h[j] = hp[lane + j * 32]; sum += h[j]; }
    #pragma unroll
    for (int o = 16; o > 0; o >>= 1) sum += __shfl_xor_sync(0xffffffffu, sum, o);
    float mu = sum * (1.f / 192.f);

    float s2 = 0.f;
    #pragma unroll
    for (int j = 0; j < 6; j++) { float d = h[j] - mu; s2 += d * d; }
    #pragma unroll
    for (int o = 16; o > 0; o >>= 1) s2 += __shfl_xor_sync(0xffffffffu, s2, o);
    float invstd = rsqrtf(s2 * (1.f / 192.f) + 1e-12f);

    float* op = &out[(size_t)row * DD];
    #pragma unroll
    for (int j = 0; j < 6; j++) {
        int cc = lane + j * 32;
        op[cc] = (h[j] - mu) * invstd * ln_g[cc] + ln_b[cc];
    }
}

// ---------------- launch ---------------------------------------------------
extern "C" void kernel_launch(void* const* d_in, const int* in_sizes, int n_in,
                              void* d_out, int out_size)
{
    const float* x     = (const float*)d_in[0];
    const float* mask0 = (const float*)d_in[1];
    const float* bq    = (const float*)d_in[3];
    const float* bk    = (const float*)d_in[5];
    const float* bv    = (const float*)d_in[7];
    const float* bo    = (const float*)d_in[9];
    const float* ln_g  = (const float*)d_in[10];
    const float* ln_b  = (const float*)d_in[11];
    float* out = (float*)d_out;

    __half *pqh, *pkh, *pvh, *pxh, *pch;
    float  *phf;
    cudaGetSymbolAddress((void**)&pqh, g_qh);
    cudaGetSymbolAddress((void**)&pkh, g_kh);
    cudaGetSymbolAddress((void**)&pvh, g_vh);
    cudaGetSymbolAddress((void**)&pxh, g_xh);
    cudaGetSymbolAddress((void**)&pch, g_ctxh);
    cudaGetSymbolAddress((void**)&phf, g_hf);

    cudaFuncSetAttribute(gemm_fp16, cudaFuncAttributeMaxDynamicSharedMemorySize,
                         GEMM_SMEM);

    const float qscale = 0.28867513459481287f;  // 1/sqrt(12)

    cvt_weights<<<4 * WELTS / 4 / 256, 256>>>((const float*)d_in[2],
                                              (const float*)d_in[4],
                                              (const float*)d_in[6],
                                              (const float*)d_in[8]);
    cvt_x<<<NROWS * DD / 4 / 256, 256>>>(x);

    // Fused QKV: fp16 outputs
    GemmArgs qkv;
    qkv.plane[0] = 0; qkv.plane[1] = 1; qkv.plane[2] = 2;
    qkv.bias[0] = bq; qkv.bias[1] = bk; qkv.bias[2] = bv;
    qkv.out[0] = pqh; qkv.out[1] = pkh; qkv.out[2] = pvh;
    qkv.scale[0] = qscale; qkv.scale[1] = 1.f; qkv.scale[2] = 1.f;
    qkv.res = nullptr;
    qkv.out_half = 1;
    dim3 qkv_grid(3 * DD / BN, NROWS / BM);     // (9, 1024)
    gemm_fp16<<<qkv_grid, 256, GEMM_SMEM>>>(pxh, qkv);

    band_attn<<<BATCH * (SEQ / TS), 256>>>(mask0);

    // Output projection + residual -> fp32 h
    GemmArgs og;
    og.plane[0] = 3; og.plane[1] = 3; og.plane[2] = 3;
    og.bias[0] = bo; og.bias[1] = bo; og.bias[2] = bo;
    og.out[0] = phf; og.out[1] = phf; og.out[2] = phf;
    og.scale[0] = 1.f; og.scale[1] = 1.f; og.scale[2] = 1.f;
    og.res = x;
    og.out_half = 0;
    dim3 o_grid(DD / BN, NROWS / BM);           // (3, 1024)
    gemm_fp16<<<o_grid, 256, GEMM_SMEM>>>(pch, og);

    layernorm<<<NROWS / 8, 256>>>(ln_g, ln_b, out);
}